// round 8
// baseline (speedup 1.0000x reference)
#include <cuda_runtime.h>
#include <math.h>
#include <stdint.h>

#define T_SEQ   4096
#define C_DIM   1024
#define NHEADS  16
#define HDIM    64

// ---------------- scratch (static device globals; no allocation) -------------
__device__ float g_normed[T_SEQ * C_DIM];
__device__ float g_q[T_SEQ * C_DIM];
__device__ float g_k[T_SEQ * C_DIM];
__device__ float g_v[T_SEQ * C_DIM];
__device__ float g_att[T_SEQ * C_DIM];

// ================= helpers ===================================================
__device__ __forceinline__ uint32_t smem_u32(const void* p) {
    uint32_t a;
    asm("{ .reg .u64 t; cvta.to.shared.u64 t, %1; cvt.u32.u64 %0, t; }"
        : "=r"(a) : "l"(p));
    return a;
}

__device__ __forceinline__ void cp_async16(uint32_t saddr, const void* gptr) {
    asm volatile("cp.async.cg.shared.global [%0], [%1], 16;"
                 :: "r"(saddr), "l"(gptr));
}
__device__ __forceinline__ void cp_commit() {
    asm volatile("cp.async.commit_group;");
}
template <int N>
__device__ __forceinline__ void cp_wait() {
    asm volatile("cp.async.wait_group %0;" :: "n"(N));
}

__device__ __forceinline__ void split_tf32(float a, float& hi, float& lo)
{
    uint32_t h;
    asm("cvt.rna.tf32.f32 %0, %1;" : "=r"(h) : "f"(a));
    hi = __uint_as_float(h);
    float r = a - hi;
    uint32_t l2;
    asm("cvt.rna.tf32.f32 %0, %1;" : "=r"(l2) : "f"(r));
    lo = __uint_as_float(l2);
}

__device__ __forceinline__ float to_tf32(float a)
{
    uint32_t u;
    asm("cvt.rna.tf32.f32 %0, %1;" : "=r"(u) : "f"(a));
    return __uint_as_float(u);
}

// m16n8k8 tf32 mma
__device__ __forceinline__ void mma_tf32(float d[4],
                                         float a0, float a1, float a2, float a3,
                                         float b0, float b1)
{
    asm volatile(
        "mma.sync.aligned.m16n8k8.row.col.f32.tf32.tf32.f32 "
        "{%0,%1,%2,%3}, {%4,%5,%6,%7}, {%8,%9}, {%0,%1,%2,%3};"
        : "+f"(d[0]), "+f"(d[1]), "+f"(d[2]), "+f"(d[3])
        : "r"(__float_as_uint(a0)), "r"(__float_as_uint(a1)),
          "r"(__float_as_uint(a2)), "r"(__float_as_uint(a3)),
          "r"(__float_as_uint(b0)), "r"(__float_as_uint(b1)));
}

// ================= HMMA tf32 GEMM: C[M,N] = A[M,K] @ B[N,K]^T (+Res) =========
// 128x128 CTA tile, BK=64, 512 threads (16 warps, 4x4), warp tile 32x32.
// Raw fp32 in smem via cp.async; tf32 split (Ahi+Alo)*Bhi at fragment load.
#define G_BM 128
#define G_BN 128
#define G_BK 64
#define G_SK 68                                // padded k-stride (floats)
#define G_PLANE (128 * G_SK)                   // floats per plane
#define G_STAGE (2 * G_PLANE)                  // A + B planes
#define G_SMEM_TOTAL (2 * G_STAGE * 4)         // 139264 bytes

__device__ __forceinline__ void issue_tile(uint32_t s_a, uint32_t s_b,
                                           const float* __restrict__ Ag,
                                           const float* __restrict__ Bg,
                                           int K, int k0, int tid)
{
#pragma unroll
    for (int t = 0; t < 4; t++) {
        int idx = tid + t * 512;          // 2048 float4 per tile
        int row = idx >> 4;               // 16 float4 per 64-float row
        int c4 = idx & 15;
        uint32_t soff = (uint32_t)(row * G_SK + c4 * 4) * 4u;
        cp_async16(s_a + soff, Ag + (size_t)row * K + k0 + c4 * 4);
        cp_async16(s_b + soff, Bg + (size_t)row * K + k0 + c4 * 4);
    }
}

__global__ __launch_bounds__(512, 1)
void gemm_mma_kernel(const float* __restrict__ A, const float* __restrict__ B,
                     const float* __restrict__ Res, float* __restrict__ Cm,
                     int M, int N, int K)
{
    extern __shared__ float sm[];
    uint32_t smem_base = smem_u32(sm);
    int tid = threadIdx.x;
    int wid = tid >> 5;
    int lane = tid & 31;
    int gid = lane >> 2;
    int tig = lane & 3;
    int wm = wid & 3;          // 4 m-slabs of 32 rows
    int wn = wid >> 2;         // 4 n-slabs of 32 cols

    const float* Atile = A + (size_t)(blockIdx.y * G_BM) * K;
    const float* Btile = B + (size_t)(blockIdx.x * G_BN) * K;

    float acc[2][4][4];
#pragma unroll
    for (int mi = 0; mi < 2; mi++)
#pragma unroll
        for (int ni = 0; ni < 4; ni++)
#pragma unroll
            for (int e = 0; e < 4; e++) acc[mi][ni][e] = 0.f;

    const int NCHUNK = K / G_BK;   // 16

    // prologue: chunk 0 -> stage 0
    issue_tile(smem_base, smem_base + G_PLANE * 4u, Atile, Btile, K, 0, tid);
    cp_commit();

    for (int kc = 0; kc < NCHUNK; kc++) {
        int cur = kc & 1;
        if (kc + 1 < NCHUNK) {
            uint32_t sb = smem_base + (uint32_t)(1 - cur) * G_STAGE * 4u;
            issue_tile(sb, sb + G_PLANE * 4u, Atile, Btile, K, (kc + 1) * G_BK, tid);
            cp_commit();
            cp_wait<1>();
        } else {
            cp_wait<0>();
        }
        __syncthreads();   // stage cur visible to all

        const float* As = sm + cur * G_STAGE;
        const float* Bs = As + G_PLANE;

#pragma unroll
        for (int ks = 0; ks < 8; ks++) {
            int kk = ks * 8;
            float ah[2][4], al[2][4];
#pragma unroll
            for (int mi = 0; mi < 2; mi++) {
                int mrow = wm * 32 + mi * 16 + gid;
                int base = mrow * G_SK + kk + tig;
                float r0 = As[base];
                float r1 = As[base + 8 * G_SK];
                float r2 = As[base + 4];
                float r3 = As[base + 8 * G_SK + 4];
                split_tf32(r0, ah[mi][0], al[mi][0]);
                split_tf32(r1, ah[mi][1], al[mi][1]);
                split_tf32(r2, ah[mi][2], al[mi][2]);
                split_tf32(r3, ah[mi][3], al[mi][3]);
            }
            float bh[4][2];
#pragma unroll
            for (int ni = 0; ni < 4; ni++) {
                int ncol = wn * 32 + ni * 8 + gid;
                int base = ncol * G_SK + kk + tig;
                bh[ni][0] = to_tf32(Bs[base]);
                bh[ni][1] = to_tf32(Bs[base + 4]);
            }
#pragma unroll
            for (int mi = 0; mi < 2; mi++)
#pragma unroll
                for (int ni = 0; ni < 4; ni++) {
                    mma_tf32(acc[mi][ni], ah[mi][0], ah[mi][1], ah[mi][2], ah[mi][3],
                             bh[ni][0], bh[ni][1]);
                    mma_tf32(acc[mi][ni], al[mi][0], al[mi][1], al[mi][2], al[mi][3],
                             bh[ni][0], bh[ni][1]);
                }
        }
        __syncthreads();   // all reads of stage cur done before it is refilled
    }

    // epilogue
#pragma unroll
    for (int mi = 0; mi < 2; mi++) {
        int row0 = blockIdx.y * G_BM + wm * 32 + mi * 16 + gid;
#pragma unroll
        for (int ni = 0; ni < 4; ni++) {
            int col = blockIdx.x * G_BN + wn * 32 + ni * 8 + 2 * tig;
            float* d0 = Cm + (size_t)row0 * N + col;
            float* d1 = Cm + (size_t)(row0 + 8) * N + col;
            float2 v0 = make_float2(acc[mi][ni][0], acc[mi][ni][1]);
            float2 v1 = make_float2(acc[mi][ni][2], acc[mi][ni][3]);
            if (Res) {
                const float2 r0 = *reinterpret_cast<const float2*>(Res + (size_t)row0 * N + col);
                const float2 r1 = *reinterpret_cast<const float2*>(Res + (size_t)(row0 + 8) * N + col);
                v0.x += r0.x; v0.y += r0.y;
                v1.x += r1.x; v1.y += r1.y;
            }
            *reinterpret_cast<float2*>(d0) = v0;
            *reinterpret_cast<float2*>(d1) = v1;
        }
    }
}

// ---------------- RMSNorm ----------------------------------------------------
__global__ void rmsnorm_kernel(const float* __restrict__ x,
                               const float* __restrict__ w,
                               float* __restrict__ out)
{
    int row = blockIdx.x;
    const float4* xr = reinterpret_cast<const float4*>(x + (size_t)row * C_DIM);
    float ss = 0.f;
    for (int i = threadIdx.x; i < C_DIM / 4; i += blockDim.x) {
        float4 v = xr[i];
        ss += v.x * v.x + v.y * v.y + v.z * v.z + v.w * v.w;
    }
#pragma unroll
    for (int o = 16; o; o >>= 1) ss += __shfl_xor_sync(0xffffffffu, ss, o);

    __shared__ float red[8];
    __shared__ float s_inv;
    if ((threadIdx.x & 31) == 0) red[threadIdx.x >> 5] = ss;
    __syncthreads();
    if (threadIdx.x == 0) {
        float tot = 0.f;
        int nw = blockDim.x >> 5;
        for (int i = 0; i < nw; i++) tot += red[i];
        s_inv = rsqrtf(tot * (1.0f / C_DIM) + 1e-6f);
    }
    __syncthreads();
    float inv = s_inv;
    const float4* wr = reinterpret_cast<const float4*>(w);
    float4* outr = reinterpret_cast<float4*>(out + (size_t)row * C_DIM);
    for (int i = threadIdx.x; i < C_DIM / 4; i += blockDim.x) {
        float4 v = xr[i], ww = wr[i];
        v.x = v.x * inv * ww.x;
        v.y = v.y * inv * ww.y;
        v.z = v.z * inv * ww.z;
        v.w = v.w * inv * ww.w;
        outr[i] = v;
    }
}

// ---------------- RoPE (applied to q and k in place) -------------------------
__global__ void rope_kernel(float* __restrict__ q, float* __restrict__ k)
{
    int idx = blockIdx.x * blockDim.x + threadIdx.x;
    if (idx >= T_SEQ * NHEADS * 32) return;
    int i = idx & 31;
    int h = (idx >> 5) & (NHEADS - 1);
    int t = idx >> 9;
    float freq = powf(10000.0f, -(float)(2 * i) * (1.0f / 64.0f));
    float f = (float)t * freq;
    float s, c;
    sincosf(f, &s, &c);
    int base = t * C_DIM + h * HDIM;
    float q1 = q[base + i], q2 = q[base + i + 32];
    q[base + i]      = q1 * c - q2 * s;
    q[base + i + 32] = q2 * c + q1 * s;
    float k1 = k[base + i], k2 = k[base + i + 32];
    k[base + i]      = k1 * c - k2 * s;
    k[base + i + 32] = k2 * c + k1 * s;
}

// ---------------- Flash attention on tensor cores ----------------------------
#define FQ_STR 68
#define FV_STR 72
#define F_SMEM_BYTES ((4 * 64 * FQ_STR + 64 * FV_STR) * 4)

__global__ __launch_bounds__(128, 2)
void flash_mma_kernel(const float* __restrict__ Qg, const float* __restrict__ Kg,
                      const float* __restrict__ Vg, float* __restrict__ Og)
{
    extern __shared__ float sm[];
    float* Qhi = sm;
    float* Qlo = Qhi + 64 * FQ_STR;
    float* Kh  = Qlo + 64 * FQ_STR;
    float* Ps  = Kh  + 64 * FQ_STR;
    float* Vs  = Ps  + 64 * FQ_STR;

    int qt = (gridDim.x - 1) - blockIdx.x;
    int h  = blockIdx.y;
    int tid = threadIdx.x;
    int wid = tid >> 5;
    int lane = tid & 31;
    int gid = lane >> 2;
    int tig = lane & 3;
    int wr0 = wid * 16;

#pragma unroll
    for (int v = 0; v < 8; v++) {
        int i = tid + v * 128;
        int row = i >> 4;
        int c4 = i & 15;
        float4 q4 = *reinterpret_cast<const float4*>(
            Qg + (size_t)(qt * 64 + row) * C_DIM + h * HDIM + c4 * 4);
        q4.x *= 0.125f; q4.y *= 0.125f; q4.z *= 0.125f; q4.w *= 0.125f;
        float4 h4, l4;
        split_tf32(q4.x, h4.x, l4.x);
        split_tf32(q4.y, h4.y, l4.y);
        split_tf32(q4.z, h4.z, l4.z);
        split_tf32(q4.w, h4.w, l4.w);
        *reinterpret_cast<float4*>(Qhi + row * FQ_STR + c4 * 4) = h4;
        *reinterpret_cast<float4*>(Qlo + row * FQ_STR + c4 * 4) = l4;
    }

    float oacc[8][4];
#pragma unroll
    for (int ni = 0; ni < 8; ni++)
#pragma unroll
        for (int e = 0; e < 4; e++) oacc[ni][e] = 0.f;
    float m0 = -INFINITY, m1 = -INFINITY;
    float l0 = 0.f, l1 = 0.f;

    for (int j = 0; j <= qt; j++) {
        __syncthreads();

#pragma unroll
        for (int v = 0; v < 8; v++) {
            int i = tid + v * 128;
            int row = i >> 4;
            int c4 = i & 15;
            float4 k4 = *reinterpret_cast<const float4*>(
                Kg + (size_t)(j * 64 + row) * C_DIM + h * HDIM + c4 * 4);
            k4.x = to_tf32(k4.x); k4.y = to_tf32(k4.y);
            k4.z = to_tf32(k4.z); k4.w = to_tf32(k4.w);
            *reinterpret_cast<float4*>(Kh + row * FQ_STR + c4 * 4) = k4;
            float4 v4 = *reinterpret_cast<const float4*>(
                Vg + (size_t)(j * 64 + row) * C_DIM + h * HDIM + c4 * 4);
            v4.x = to_tf32(v4.x); v4.y = to_tf32(v4.y);
            v4.z = to_tf32(v4.z); v4.w = to_tf32(v4.w);
            *reinterpret_cast<float4*>(Vs + row * FV_STR + c4 * 4) = v4;
        }
        __syncthreads();

        float sacc[8][4];
#pragma unroll
        for (int ni = 0; ni < 8; ni++)
#pragma unroll
            for (int e = 0; e < 4; e++) sacc[ni][e] = 0.f;

#pragma unroll
        for (int kk = 0; kk < 8; kk++) {
            int kb = kk * 8;
            int abase = (wr0 + gid) * FQ_STR + kb + tig;
            float qh0 = Qhi[abase];
            float qh1 = Qhi[abase + 8 * FQ_STR];
            float qh2 = Qhi[abase + 4];
            float qh3 = Qhi[abase + 8 * FQ_STR + 4];
            float ql0 = Qlo[abase];
            float ql1 = Qlo[abase + 8 * FQ_STR];
            float ql2 = Qlo[abase + 4];
            float ql3 = Qlo[abase + 8 * FQ_STR + 4];
#pragma unroll
            for (int ni = 0; ni < 8; ni++) {
                int bbase = (ni * 8 + gid) * FQ_STR + kb + tig;
                float b0 = Kh[bbase];
                float b1 = Kh[bbase + 4];
                mma_tf32(sacc[ni], qh0, qh1, qh2, qh3, b0, b1);
                mma_tf32(sacc[ni], ql0, ql1, ql2, ql3, b0, b1);
            }
        }

        if (j == qt) {
#pragma unroll
            for (int ni = 0; ni < 8; ni++) {
                int c0 = ni * 8 + 2 * tig;
                int rA = wr0 + gid, rB = wr0 + gid + 8;
                if (c0 > rA)     sacc[ni][0] = -INFINITY;
                if (c0 + 1 > rA) sacc[ni][1] = -INFINITY;
                if (c0 > rB)     sacc[ni][2] = -INFINITY;
                if (c0 + 1 > rB) sacc[ni][3] = -INFINITY;
            }
        }

        float rm0 = -INFINITY, rm1 = -INFINITY;
#pragma unroll
        for (int ni = 0; ni < 8; ni++) {
            rm0 = fmaxf(rm0, fmaxf(sacc[ni][0], sacc[ni][1]));
            rm1 = fmaxf(rm1, fmaxf(sacc[ni][2], sacc[ni][3]));
        }
        rm0 = fmaxf(rm0, __shfl_xor_sync(0xffffffffu, rm0, 1));
        rm0 = fmaxf(rm0, __shfl_xor_sync(0xffffffffu, rm0, 2));
        rm1 = fmaxf(rm1, __shfl_xor_sync(0xffffffffu, rm1, 1));
        rm1 = fmaxf(rm1, __shfl_xor_sync(0xffffffffu, rm1, 2));

        float mn0 = fmaxf(m0, rm0);
        float mn1 = fmaxf(m1, rm1);
        float alpha0 = __expf(m0 - mn0);
        float alpha1 = __expf(m1 - mn1);
        m0 = mn0; m1 = mn1;

        float rs0 = 0.f, rs1 = 0.f;
#pragma unroll
        for (int ni = 0; ni < 8; ni++) {
            float p0 = __expf(sacc[ni][0] - mn0);
            float p1 = __expf(sacc[ni][1] - mn0);
            float p2 = __expf(sacc[ni][2] - mn1);
            float p3 = __expf(sacc[ni][3] - mn1);
            rs0 += p0 + p1;
            rs1 += p2 + p3;
            int c0 = ni * 8 + 2 * tig;
            *reinterpret_cast<float2*>(Ps + (wr0 + gid) * FQ_STR + c0) =
                make_float2(to_tf32(p0), to_tf32(p1));
            *reinterpret_cast<float2*>(Ps + (wr0 + gid + 8) * FQ_STR + c0) =
                make_float2(to_tf32(p2), to_tf32(p3));
        }
        rs0 += __shfl_xor_sync(0xffffffffu, rs0, 1);
        rs0 += __shfl_xor_sync(0xffffffffu, rs0, 2);
        rs1 += __shfl_xor_sync(0xffffffffu, rs1, 1);
        rs1 += __shfl_xor_sync(0xffffffffu, rs1, 2);
        l0 = l0 * alpha0 + rs0;
        l1 = l1 * alpha1 + rs1;

#pragma unroll
        for (int ni = 0; ni < 8; ni++) {
            oacc[ni][0] *= alpha0; oacc[ni][1] *= alpha0;
            oacc[ni][2] *= alpha1; oacc[ni][3] *= alpha1;
        }
        __syncwarp();

#pragma unroll
        for (int kk = 0; kk < 8; kk++) {
            int kb = kk * 8;
            int abase = (wr0 + gid) * FQ_STR + kb + tig;
            float a0 = Ps[abase];
            float a1 = Ps[abase + 8 * FQ_STR];
            float a2 = Ps[abase + 4];
            float a3 = Ps[abase + 8 * FQ_STR + 4];
#pragma unroll
            for (int ni = 0; ni < 8; ni++) {
                float b0 = Vs[(kb + tig) * FV_STR + ni * 8 + gid];
                float b1 = Vs[(kb + tig + 4) * FV_STR + ni * 8 + gid];
                mma_tf32(oacc[ni], a0, a1, a2, a3, b0, b1);
            }
        }
    }

    float invl0 = 1.f / l0;
    float invl1 = 1.f / l1;
    int row0 = qt * 64 + wr0 + gid;
    int row1 = row0 + 8;
#pragma unroll
    for (int ni = 0; ni < 8; ni++) {
        int col = h * HDIM + ni * 8 + 2 * tig;
        *reinterpret_cast<float2*>(Og + (size_t)row0 * C_DIM + col) =
            make_float2(oacc[ni][0] * invl0, oacc[ni][1] * invl0);
        *reinterpret_cast<float2*>(Og + (size_t)row1 * C_DIM + col) =
            make_float2(oacc[ni][2] * invl1, oacc[ni][3] * invl1);
    }
}

// ---------------- launch -----------------------------------------------------
extern "C" void kernel_launch(void* const* d_in, const int* in_sizes, int n_in,
                              void* d_out, int out_size)
{
    const float* x      = (const float*)d_in[0];
    const float* wq     = (const float*)d_in[1];
    const float* wk     = (const float*)d_in[2];
    const float* wv     = (const float*)d_in[3];
    const float* wo     = (const float*)d_in[4];
    const float* norm_w = (const float*)d_in[5];
    float* out = (float*)d_out;

    float *normed, *q, *k, *v, *att;
    cudaGetSymbolAddress((void**)&normed, g_normed);
    cudaGetSymbolAddress((void**)&q,      g_q);
    cudaGetSymbolAddress((void**)&k,      g_k);
    cudaGetSymbolAddress((void**)&v,      g_v);
    cudaGetSymbolAddress((void**)&att,    g_att);

    // 1) RMSNorm
    rmsnorm_kernel<<<T_SEQ, 256>>>(x, norm_w, normed);

    // 2) Q/K/V projections (mma.sync tf32, 2-term split, cp.async pipeline)
    cudaFuncSetAttribute(gemm_mma_kernel, cudaFuncAttributeMaxDynamicSharedMemorySize,
                         G_SMEM_TOTAL);
    dim3 gdim(C_DIM / G_BN, T_SEQ / G_BM);
    gemm_mma_kernel<<<gdim, 512, G_SMEM_TOTAL>>>(normed, wq, nullptr, q, T_SEQ, C_DIM, C_DIM);
    gemm_mma_kernel<<<gdim, 512, G_SMEM_TOTAL>>>(normed, wk, nullptr, k, T_SEQ, C_DIM, C_DIM);
    gemm_mma_kernel<<<gdim, 512, G_SMEM_TOTAL>>>(normed, wv, nullptr, v, T_SEQ, C_DIM, C_DIM);

    // 3) RoPE on q,k
    int nrope = T_SEQ * NHEADS * 32;
    rope_kernel<<<(nrope + 255) / 256, 256>>>(q, k);

    // 4) causal flash attention on tensor cores
    cudaFuncSetAttribute(flash_mma_kernel, cudaFuncAttributeMaxDynamicSharedMemorySize,
                         F_SMEM_BYTES);
    dim3 fgrid(T_SEQ / 64, NHEADS);
    flash_mma_kernel<<<fgrid, 128, F_SMEM_BYTES>>>(q, k, v, att);

    // 5) output projection + residual
    gemm_mma_kernel<<<gdim, 512, G_SMEM_TOTAL>>>(att, wo, x, out, T_SEQ, C_DIM, C_DIM);
}

// round 9
// speedup vs baseline: 1.1313x; 1.1313x over previous
#include <cuda_runtime.h>
#include <math.h>
#include <stdint.h>

#define T_SEQ   4096
#define C_DIM   1024
#define NHEADS  16
#define HDIM    64

// ---------------- scratch (static device globals; no allocation) -------------
__device__ float g_normed[T_SEQ * C_DIM];
__device__ float g_q[T_SEQ * C_DIM];
__device__ float g_k[T_SEQ * C_DIM];
__device__ float g_v[T_SEQ * C_DIM];
__device__ float g_att[T_SEQ * C_DIM];

// ================= tf32 helpers ==============================================
__device__ __forceinline__ void split_tf32(float a, float& hi, float& lo)
{
    uint32_t h;
    asm("cvt.rna.tf32.f32 %0, %1;" : "=r"(h) : "f"(a));
    hi = __uint_as_float(h);
    float r = a - hi;
    uint32_t l2;
    asm("cvt.rna.tf32.f32 %0, %1;" : "=r"(l2) : "f"(r));
    lo = __uint_as_float(l2);
}

__device__ __forceinline__ float to_tf32(float a)
{
    uint32_t u;
    asm("cvt.rna.tf32.f32 %0, %1;" : "=r"(u) : "f"(a));
    return __uint_as_float(u);
}

// m16n8k8 tf32 mma (sm_80+ baseline PTX, runs on tensor pipe)
__device__ __forceinline__ void mma_tf32(float d[4],
                                         float a0, float a1, float a2, float a3,
                                         float b0, float b1)
{
    asm volatile(
        "mma.sync.aligned.m16n8k8.row.col.f32.tf32.tf32.f32 "
        "{%0,%1,%2,%3}, {%4,%5,%6,%7}, {%8,%9}, {%0,%1,%2,%3};"
        : "+f"(d[0]), "+f"(d[1]), "+f"(d[2]), "+f"(d[3])
        : "r"(__float_as_uint(a0)), "r"(__float_as_uint(a1)),
          "r"(__float_as_uint(a2)), "r"(__float_as_uint(a3)),
          "r"(__float_as_uint(b0)), "r"(__float_as_uint(b1)));
}

// ================= HMMA tf32 GEMM: C[M,N] = A[M,K] @ B[N,K]^T (+Res) =========
// 2-term split: Ahi*Bhi + Alo*Bhi (B rounded to tf32). 3 smem planes.
// (R7 configuration: 256 threads, warp tile 64x32, STS-time split — 130us.)
#define G_BM 128
#define G_BN 128
#define G_BK 32
#define G_SK 36
#define G_PLANE (128 * G_SK)
#define G_BUF   (3 * G_PLANE)            // Ahi, Alo, Bhi
#define G_SMEM_TOTAL (2 * G_BUF * 4)     // 110592 bytes

__device__ __forceinline__ void ldg_tile(const float* __restrict__ G, int ldk,
                                         int k0, int tid, float4 r[4])
{
#pragma unroll
    for (int v = 0; v < 4; v++) {
        int i = tid + v * 256;
        int row = i >> 3;
        int c4 = i & 7;
        r[v] = *reinterpret_cast<const float4*>(G + (size_t)row * ldk + k0 + c4 * 4);
    }
}

__device__ __forceinline__ void sts_split(const float4 r[4], float* __restrict__ hi,
                                          float* __restrict__ lo, int tid)
{
#pragma unroll
    for (int v = 0; v < 4; v++) {
        int i = tid + v * 256;
        int row = i >> 3;
        int c4 = i & 7;
        int off = row * G_SK + c4 * 4;
        float4 h4, l4;
        split_tf32(r[v].x, h4.x, l4.x);
        split_tf32(r[v].y, h4.y, l4.y);
        split_tf32(r[v].z, h4.z, l4.z);
        split_tf32(r[v].w, h4.w, l4.w);
        *reinterpret_cast<float4*>(hi + off) = h4;
        *reinterpret_cast<float4*>(lo + off) = l4;
    }
}

__device__ __forceinline__ void sts_round(const float4 r[4], float* __restrict__ hi,
                                          int tid)
{
#pragma unroll
    for (int v = 0; v < 4; v++) {
        int i = tid + v * 256;
        int row = i >> 3;
        int c4 = i & 7;
        int off = row * G_SK + c4 * 4;
        float4 h4;
        h4.x = to_tf32(r[v].x);
        h4.y = to_tf32(r[v].y);
        h4.z = to_tf32(r[v].z);
        h4.w = to_tf32(r[v].w);
        *reinterpret_cast<float4*>(hi + off) = h4;
    }
}

__global__ __launch_bounds__(256, 1)
void gemm_mma_kernel(const float* __restrict__ A, const float* __restrict__ B,
                     const float* __restrict__ Res, float* __restrict__ Cm,
                     int M, int N, int K)
{
    extern __shared__ float sm[];
    int tid = threadIdx.x;
    int wid = tid >> 5;
    int lane = tid & 31;
    int gid = lane >> 2;
    int tig = lane & 3;
    int wm = wid & 1;
    int wn = wid >> 1;

    const float* Atile = A + (size_t)(blockIdx.y * G_BM) * K;
    const float* Btile = B + (size_t)(blockIdx.x * G_BN) * K;

    float acc[4][4][4];
#pragma unroll
    for (int mi = 0; mi < 4; mi++)
#pragma unroll
        for (int ni = 0; ni < 4; ni++)
#pragma unroll
            for (int e = 0; e < 4; e++) acc[mi][ni][e] = 0.f;

    const int NCHUNK = K / G_BK;

    float4 ra[4], rb[4];
    ldg_tile(Atile, K, 0, tid, ra);
    ldg_tile(Btile, K, 0, tid, rb);
    {
        float* base = sm;
        sts_split(ra, base + 0 * G_PLANE, base + 1 * G_PLANE, tid);
        sts_round(rb, base + 2 * G_PLANE, tid);
    }
    __syncthreads();

    for (int kc = 0; kc < NCHUNK; kc++) {
        int cur = kc & 1;
        if (kc + 1 < NCHUNK) {
            ldg_tile(Atile, K, (kc + 1) * G_BK, tid, ra);
            ldg_tile(Btile, K, (kc + 1) * G_BK, tid, rb);
        }

        const float* Ahi = sm + cur * G_BUF;
        const float* Alo = Ahi + G_PLANE;
        const float* Bhi = Alo + G_PLANE;

#pragma unroll
        for (int ks = 0; ks < 4; ks++) {
            int kk = ks * 8;
            float Ah[4][4], Al[4][4];
#pragma unroll
            for (int mi = 0; mi < 4; mi++) {
                int mrow = wm * 64 + mi * 16 + gid;
                int base = mrow * G_SK + kk + tig;
                Ah[mi][0] = Ahi[base];
                Ah[mi][1] = Ahi[base + 8 * G_SK];
                Ah[mi][2] = Ahi[base + 4];
                Ah[mi][3] = Ahi[base + 8 * G_SK + 4];
                Al[mi][0] = Alo[base];
                Al[mi][1] = Alo[base + 8 * G_SK];
                Al[mi][2] = Alo[base + 4];
                Al[mi][3] = Alo[base + 8 * G_SK + 4];
            }
            float Bh[4][2];
#pragma unroll
            for (int ni = 0; ni < 4; ni++) {
                int ncol = wn * 32 + ni * 8 + gid;
                int base = ncol * G_SK + kk + tig;
                Bh[ni][0] = Bhi[base];
                Bh[ni][1] = Bhi[base + 4];
            }
#pragma unroll
            for (int mi = 0; mi < 4; mi++)
#pragma unroll
                for (int ni = 0; ni < 4; ni++) {
                    mma_tf32(acc[mi][ni], Ah[mi][0], Ah[mi][1], Ah[mi][2], Ah[mi][3],
                             Bh[ni][0], Bh[ni][1]);
                    mma_tf32(acc[mi][ni], Al[mi][0], Al[mi][1], Al[mi][2], Al[mi][3],
                             Bh[ni][0], Bh[ni][1]);
                }
        }

        if (kc + 1 < NCHUNK) {
            float* base = sm + (1 - cur) * G_BUF;
            sts_split(ra, base + 0 * G_PLANE, base + 1 * G_PLANE, tid);
            sts_round(rb, base + 2 * G_PLANE, tid);
        }
        __syncthreads();
    }

#pragma unroll
    for (int mi = 0; mi < 4; mi++) {
        int row0 = blockIdx.y * G_BM + wm * 64 + mi * 16 + gid;
#pragma unroll
        for (int ni = 0; ni < 4; ni++) {
            int col = blockIdx.x * G_BN + wn * 32 + ni * 8 + 2 * tig;
            float* d0 = Cm + (size_t)row0 * N + col;
            float* d1 = Cm + (size_t)(row0 + 8) * N + col;
            float2 v0 = make_float2(acc[mi][ni][0], acc[mi][ni][1]);
            float2 v1 = make_float2(acc[mi][ni][2], acc[mi][ni][3]);
            if (Res) {
                const float2 r0 = *reinterpret_cast<const float2*>(Res + (size_t)row0 * N + col);
                const float2 r1 = *reinterpret_cast<const float2*>(Res + (size_t)(row0 + 8) * N + col);
                v0.x += r0.x; v0.y += r0.y;
                v1.x += r1.x; v1.y += r1.y;
            }
            *reinterpret_cast<float2*>(d0) = v0;
            *reinterpret_cast<float2*>(d1) = v1;
        }
    }
}

// ---------------- RMSNorm ----------------------------------------------------
__global__ void rmsnorm_kernel(const float* __restrict__ x,
                               const float* __restrict__ w,
                               float* __restrict__ out)
{
    int row = blockIdx.x;
    const float4* xr = reinterpret_cast<const float4*>(x + (size_t)row * C_DIM);
    float ss = 0.f;
    for (int i = threadIdx.x; i < C_DIM / 4; i += blockDim.x) {
        float4 v = xr[i];
        ss += v.x * v.x + v.y * v.y + v.z * v.z + v.w * v.w;
    }
#pragma unroll
    for (int o = 16; o; o >>= 1) ss += __shfl_xor_sync(0xffffffffu, ss, o);

    __shared__ float red[8];
    __shared__ float s_inv;
    if ((threadIdx.x & 31) == 0) red[threadIdx.x >> 5] = ss;
    __syncthreads();
    if (threadIdx.x == 0) {
        float tot = 0.f;
        int nw = blockDim.x >> 5;
        for (int i = 0; i < nw; i++) tot += red[i];
        s_inv = rsqrtf(tot * (1.0f / C_DIM) + 1e-6f);
    }
    __syncthreads();
    float inv = s_inv;
    const float4* wr = reinterpret_cast<const float4*>(w);
    float4* outr = reinterpret_cast<float4*>(out + (size_t)row * C_DIM);
    for (int i = threadIdx.x; i < C_DIM / 4; i += blockDim.x) {
        float4 v = xr[i], ww = wr[i];
        v.x = v.x * inv * ww.x;
        v.y = v.y * inv * ww.y;
        v.z = v.z * inv * ww.z;
        v.w = v.w * inv * ww.w;
        outr[i] = v;
    }
}

// ---------------- RoPE (applied to q and k in place) -------------------------
__global__ void rope_kernel(float* __restrict__ q, float* __restrict__ k)
{
    int idx = blockIdx.x * blockDim.x + threadIdx.x;
    if (idx >= T_SEQ * NHEADS * 32) return;
    int i = idx & 31;
    int h = (idx >> 5) & (NHEADS - 1);
    int t = idx >> 9;
    float freq = powf(10000.0f, -(float)(2 * i) * (1.0f / 64.0f));
    float f = (float)t * freq;
    float s, c;
    sincosf(f, &s, &c);
    int base = t * C_DIM + h * HDIM;
    float q1 = q[base + i], q2 = q[base + i + 32];
    q[base + i]      = q1 * c - q2 * s;
    q[base + i + 32] = q2 * c + q1 * s;
    float k1 = k[base + i], k2 = k[base + i + 32];
    k[base + i]      = k1 * c - k2 * s;
    k[base + i + 32] = k2 * c + k1 * s;
}

// ---------------- Flash attention on tensor cores ----------------------------
// Br=Bc=64, 4 warps; warp w owns rows [w*16, w*16+16).
// 1-term QK^T (Q and K both tf32-rounded; K already was — error only ~sqrt(2)x).
// 4 smem planes -> 70656 B/CTA -> 3 CTAs/SM.
#define FQ_STR 68
#define FV_STR 72
#define F_SMEM_BYTES ((3 * 64 * FQ_STR + 64 * FV_STR) * 4)   // 70656

__global__ __launch_bounds__(128, 3)
void flash_mma_kernel(const float* __restrict__ Qg, const float* __restrict__ Kg,
                      const float* __restrict__ Vg, float* __restrict__ Og)
{
    extern __shared__ float sm[];
    float* Qs = sm;
    float* Kh = Qs + 64 * FQ_STR;
    float* Ps = Kh + 64 * FQ_STR;
    float* Vs = Ps + 64 * FQ_STR;

    int qt = (gridDim.x - 1) - blockIdx.x;   // heavy tiles first
    int h  = blockIdx.y;
    int tid = threadIdx.x;
    int wid = tid >> 5;
    int lane = tid & 31;
    int gid = lane >> 2;
    int tig = lane & 3;
    int wr0 = wid * 16;

    // ---- load Q tile (scale by 0.125, round to tf32) ----
#pragma unroll
    for (int v = 0; v < 8; v++) {
        int i = tid + v * 128;
        int row = i >> 4;
        int c4 = i & 15;
        float4 q4 = *reinterpret_cast<const float4*>(
            Qg + (size_t)(qt * 64 + row) * C_DIM + h * HDIM + c4 * 4);
        q4.x = to_tf32(q4.x * 0.125f);
        q4.y = to_tf32(q4.y * 0.125f);
        q4.z = to_tf32(q4.z * 0.125f);
        q4.w = to_tf32(q4.w * 0.125f);
        *reinterpret_cast<float4*>(Qs + row * FQ_STR + c4 * 4) = q4;
    }

    float oacc[8][4];
#pragma unroll
    for (int ni = 0; ni < 8; ni++)
#pragma unroll
        for (int e = 0; e < 4; e++) oacc[ni][e] = 0.f;
    float m0 = -INFINITY, m1 = -INFINITY;
    float l0 = 0.f, l1 = 0.f;

    for (int j = 0; j <= qt; j++) {
        __syncthreads();   // previous tile's smem reads complete (and Q on iter 0)

#pragma unroll
        for (int v = 0; v < 8; v++) {
            int i = tid + v * 128;
            int row = i >> 4;
            int c4 = i & 15;
            float4 k4 = *reinterpret_cast<const float4*>(
                Kg + (size_t)(j * 64 + row) * C_DIM + h * HDIM + c4 * 4);
            k4.x = to_tf32(k4.x); k4.y = to_tf32(k4.y);
            k4.z = to_tf32(k4.z); k4.w = to_tf32(k4.w);
            *reinterpret_cast<float4*>(Kh + row * FQ_STR + c4 * 4) = k4;
            float4 v4 = *reinterpret_cast<const float4*>(
                Vg + (size_t)(j * 64 + row) * C_DIM + h * HDIM + c4 * 4);
            v4.x = to_tf32(v4.x); v4.y = to_tf32(v4.y);
            v4.z = to_tf32(v4.z); v4.w = to_tf32(v4.w);
            *reinterpret_cast<float4*>(Vs + row * FV_STR + c4 * 4) = v4;
        }
        __syncthreads();

        // ---- S = Q K^T (single term) ----
        float sacc[8][4];
#pragma unroll
        for (int ni = 0; ni < 8; ni++)
#pragma unroll
            for (int e = 0; e < 4; e++) sacc[ni][e] = 0.f;

#pragma unroll
        for (int kk = 0; kk < 8; kk++) {
            int kb = kk * 8;
            int abase = (wr0 + gid) * FQ_STR + kb + tig;
            float q0 = Qs[abase];
            float q1 = Qs[abase + 8 * FQ_STR];
            float q2 = Qs[abase + 4];
            float q3 = Qs[abase + 8 * FQ_STR + 4];
#pragma unroll
            for (int ni = 0; ni < 8; ni++) {
                int bbase = (ni * 8 + gid) * FQ_STR + kb + tig;
                float b0 = Kh[bbase];
                float b1 = Kh[bbase + 4];
                mma_tf32(sacc[ni], q0, q1, q2, q3, b0, b1);
            }
        }

        if (j == qt) {
#pragma unroll
            for (int ni = 0; ni < 8; ni++) {
                int c0 = ni * 8 + 2 * tig;
                int rA = wr0 + gid, rB = wr0 + gid + 8;
                if (c0 > rA)     sacc[ni][0] = -INFINITY;
                if (c0 + 1 > rA) sacc[ni][1] = -INFINITY;
                if (c0 > rB)     sacc[ni][2] = -INFINITY;
                if (c0 + 1 > rB) sacc[ni][3] = -INFINITY;
            }
        }

        float rm0 = -INFINITY, rm1 = -INFINITY;
#pragma unroll
        for (int ni = 0; ni < 8; ni++) {
            rm0 = fmaxf(rm0, fmaxf(sacc[ni][0], sacc[ni][1]));
            rm1 = fmaxf(rm1, fmaxf(sacc[ni][2], sacc[ni][3]));
        }
        rm0 = fmaxf(rm0, __shfl_xor_sync(0xffffffffu, rm0, 1));
        rm0 = fmaxf(rm0, __shfl_xor_sync(0xffffffffu, rm0, 2));
        rm1 = fmaxf(rm1, __shfl_xor_sync(0xffffffffu, rm1, 1));
        rm1 = fmaxf(rm1, __shfl_xor_sync(0xffffffffu, rm1, 2));

        float mn0 = fmaxf(m0, rm0);
        float mn1 = fmaxf(m1, rm1);
        float alpha0 = __expf(m0 - mn0);
        float alpha1 = __expf(m1 - mn1);
        m0 = mn0; m1 = mn1;

        float rs0 = 0.f, rs1 = 0.f;
#pragma unroll
        for (int ni = 0; ni < 8; ni++) {
            float p0 = __expf(sacc[ni][0] - mn0);
            float p1 = __expf(sacc[ni][1] - mn0);
            float p2 = __expf(sacc[ni][2] - mn1);
            float p3 = __expf(sacc[ni][3] - mn1);
            rs0 += p0 + p1;
            rs1 += p2 + p3;
            int c0 = ni * 8 + 2 * tig;
            *reinterpret_cast<float2*>(Ps + (wr0 + gid) * FQ_STR + c0) =
                make_float2(to_tf32(p0), to_tf32(p1));
            *reinterpret_cast<float2*>(Ps + (wr0 + gid + 8) * FQ_STR + c0) =
                make_float2(to_tf32(p2), to_tf32(p3));
        }
        rs0 += __shfl_xor_sync(0xffffffffu, rs0, 1);
        rs0 += __shfl_xor_sync(0xffffffffu, rs0, 2);
        rs1 += __shfl_xor_sync(0xffffffffu, rs1, 1);
        rs1 += __shfl_xor_sync(0xffffffffu, rs1, 2);
        l0 = l0 * alpha0 + rs0;
        l1 = l1 * alpha1 + rs1;

#pragma unroll
        for (int ni = 0; ni < 8; ni++) {
            oacc[ni][0] *= alpha0; oacc[ni][1] *= alpha0;
            oacc[ni][2] *= alpha1; oacc[ni][3] *= alpha1;
        }
        __syncwarp();   // Ps rows of this warp visible to the whole warp

#pragma unroll
        for (int kk = 0; kk < 8; kk++) {
            int kb = kk * 8;
            int abase = (wr0 + gid) * FQ_STR + kb + tig;
            float a0 = Ps[abase];
            float a1 = Ps[abase + 8 * FQ_STR];
            float a2 = Ps[abase + 4];
            float a3 = Ps[abase + 8 * FQ_STR + 4];
#pragma unroll
            for (int ni = 0; ni < 8; ni++) {
                float b0 = Vs[(kb + tig) * FV_STR + ni * 8 + gid];
                float b1 = Vs[(kb + tig + 4) * FV_STR + ni * 8 + gid];
                mma_tf32(oacc[ni], a0, a1, a2, a3, b0, b1);
            }
        }
    }

    float invl0 = 1.f / l0;
    float invl1 = 1.f / l1;
    int row0 = qt * 64 + wr0 + gid;
    int row1 = row0 + 8;
#pragma unroll
    for (int ni = 0; ni < 8; ni++) {
        int col = h * HDIM + ni * 8 + 2 * tig;
        *reinterpret_cast<float2*>(Og + (size_t)row0 * C_DIM + col) =
            make_float2(oacc[ni][0] * invl0, oacc[ni][1] * invl0);
        *reinterpret_cast<float2*>(Og + (size_t)row1 * C_DIM + col) =
            make_float2(oacc[ni][2] * invl1, oacc[ni][3] * invl1);
    }
}

// ---------------- launch -----------------------------------------------------
extern "C" void kernel_launch(void* const* d_in, const int* in_sizes, int n_in,
                              void* d_out, int out_size)
{
    const float* x      = (const float*)d_in[0];
    const float* wq     = (const float*)d_in[1];
    const float* wk     = (const float*)d_in[2];
    const float* wv     = (const float*)d_in[3];
    const float* wo     = (const float*)d_in[4];
    const float* norm_w = (const float*)d_in[5];
    float* out = (float*)d_out;

    float *normed, *q, *k, *v, *att;
    cudaGetSymbolAddress((void**)&normed, g_normed);
    cudaGetSymbolAddress((void**)&q,      g_q);
    cudaGetSymbolAddress((void**)&k,      g_k);
    cudaGetSymbolAddress((void**)&v,      g_v);
    cudaGetSymbolAddress((void**)&att,    g_att);

    // 1) RMSNorm
    rmsnorm_kernel<<<T_SEQ, 256>>>(x, norm_w, normed);

    // 2) Q/K/V projections (mma.sync tf32, 2-term split, R7 config)
    cudaFuncSetAttribute(gemm_mma_kernel, cudaFuncAttributeMaxDynamicSharedMemorySize,
                         G_SMEM_TOTAL);
    dim3 gdim(C_DIM / G_BN, T_SEQ / G_BM);
    gemm_mma_kernel<<<gdim, 256, G_SMEM_TOTAL>>>(normed, wq, nullptr, q, T_SEQ, C_DIM, C_DIM);
    gemm_mma_kernel<<<gdim, 256, G_SMEM_TOTAL>>>(normed, wk, nullptr, k, T_SEQ, C_DIM, C_DIM);
    gemm_mma_kernel<<<gdim, 256, G_SMEM_TOTAL>>>(normed, wv, nullptr, v, T_SEQ, C_DIM, C_DIM);

    // 3) RoPE on q,k
    int nrope = T_SEQ * NHEADS * 32;
    rope_kernel<<<(nrope + 255) / 256, 256>>>(q, k);

    // 4) causal flash attention on tensor cores (1-term QK, occ=3)
    cudaFuncSetAttribute(flash_mma_kernel, cudaFuncAttributeMaxDynamicSharedMemorySize,
                         F_SMEM_BYTES);
    dim3 fgrid(T_SEQ / 64, NHEADS);
    flash_mma_kernel<<<fgrid, 128, F_SMEM_BYTES>>>(q, k, v, att);

    // 5) output projection + residual
    gemm_mma_kernel<<<gdim, 256, G_SMEM_TOTAL>>>(att, wo, x, out, T_SEQ, C_DIM, C_DIM);
}

// round 10
// speedup vs baseline: 1.3030x; 1.1518x over previous
#include <cuda_runtime.h>
#include <math.h>
#include <stdint.h>

#define T_SEQ   4096
#define C_DIM   1024
#define NHEADS  16
#define HDIM    64

// ---------------- scratch (static device globals; no allocation) -------------
__device__ float g_normed[T_SEQ * C_DIM];
__device__ float g_q[T_SEQ * C_DIM];
__device__ float g_k[T_SEQ * C_DIM];
__device__ float g_v[T_SEQ * C_DIM];
__device__ float g_att[T_SEQ * C_DIM];

// ================= tf32 helpers ==============================================
__device__ __forceinline__ void split_tf32(float a, float& hi, float& lo)
{
    uint32_t h;
    asm("cvt.rna.tf32.f32 %0, %1;" : "=r"(h) : "f"(a));
    hi = __uint_as_float(h);
    float r = a - hi;
    uint32_t l2;
    asm("cvt.rna.tf32.f32 %0, %1;" : "=r"(l2) : "f"(r));
    lo = __uint_as_float(l2);
}

__device__ __forceinline__ float to_tf32(float a)
{
    uint32_t u;
    asm("cvt.rna.tf32.f32 %0, %1;" : "=r"(u) : "f"(a));
    return __uint_as_float(u);
}

// m16n8k8 tf32 mma (sm_80+ baseline PTX, runs on tensor pipe)
__device__ __forceinline__ void mma_tf32(float d[4],
                                         float a0, float a1, float a2, float a3,
                                         float b0, float b1)
{
    asm volatile(
        "mma.sync.aligned.m16n8k8.row.col.f32.tf32.tf32.f32 "
        "{%0,%1,%2,%3}, {%4,%5,%6,%7}, {%8,%9}, {%0,%1,%2,%3};"
        : "+f"(d[0]), "+f"(d[1]), "+f"(d[2]), "+f"(d[3])
        : "r"(__float_as_uint(a0)), "r"(__float_as_uint(a1)),
          "r"(__float_as_uint(a2)), "r"(__float_as_uint(a3)),
          "r"(__float_as_uint(b0)), "r"(__float_as_uint(b1)));
}

// ================= HMMA tf32 GEMM: C[M,N] = A[M,K] @ B[N,K]^T (+Res) =========
// SPLIT_A=true : 2-term Ahi*Bhi + Alo*Bhi (3 smem planes) — O projection.
// SPLIT_A=false: 1-term pure tf32 (2 smem planes)        — Q/K/V projections.
#define G_BM 128
#define G_BN 128
#define G_BK 32
#define G_SK 36
#define G_PLANE (128 * G_SK)
#define G_SMEM_2T (2 * 3 * G_PLANE * 4)   // 110592 bytes
#define G_SMEM_1T (2 * 2 * G_PLANE * 4)   //  73728 bytes

__device__ __forceinline__ void ldg_tile(const float* __restrict__ G, int ldk,
                                         int k0, int tid, float4 r[4])
{
#pragma unroll
    for (int v = 0; v < 4; v++) {
        int i = tid + v * 256;
        int row = i >> 3;
        int c4 = i & 7;
        r[v] = *reinterpret_cast<const float4*>(G + (size_t)row * ldk + k0 + c4 * 4);
    }
}

__device__ __forceinline__ void sts_split(const float4 r[4], float* __restrict__ hi,
                                          float* __restrict__ lo, int tid)
{
#pragma unroll
    for (int v = 0; v < 4; v++) {
        int i = tid + v * 256;
        int row = i >> 3;
        int c4 = i & 7;
        int off = row * G_SK + c4 * 4;
        float4 h4, l4;
        split_tf32(r[v].x, h4.x, l4.x);
        split_tf32(r[v].y, h4.y, l4.y);
        split_tf32(r[v].z, h4.z, l4.z);
        split_tf32(r[v].w, h4.w, l4.w);
        *reinterpret_cast<float4*>(hi + off) = h4;
        *reinterpret_cast<float4*>(lo + off) = l4;
    }
}

__device__ __forceinline__ void sts_round(const float4 r[4], float* __restrict__ hi,
                                          int tid)
{
#pragma unroll
    for (int v = 0; v < 4; v++) {
        int i = tid + v * 256;
        int row = i >> 3;
        int c4 = i & 7;
        int off = row * G_SK + c4 * 4;
        float4 h4;
        h4.x = to_tf32(r[v].x);
        h4.y = to_tf32(r[v].y);
        h4.z = to_tf32(r[v].z);
        h4.w = to_tf32(r[v].w);
        *reinterpret_cast<float4*>(hi + off) = h4;
    }
}

template <bool SPLIT_A>
__global__ __launch_bounds__(256, 1)
void gemm_mma_kernel(const float* __restrict__ A, const float* __restrict__ B,
                     const float* __restrict__ Res, float* __restrict__ Cm,
                     int M, int N, int K)
{
    extern __shared__ float sm[];
    const int NPLANES = SPLIT_A ? 3 : 2;
    int tid = threadIdx.x;
    int wid = tid >> 5;
    int lane = tid & 31;
    int gid = lane >> 2;
    int tig = lane & 3;
    int wm = wid & 1;
    int wn = wid >> 1;

    const float* Atile = A + (size_t)(blockIdx.y * G_BM) * K;
    const float* Btile = B + (size_t)(blockIdx.x * G_BN) * K;

    float acc[4][4][4];
#pragma unroll
    for (int mi = 0; mi < 4; mi++)
#pragma unroll
        for (int ni = 0; ni < 4; ni++)
#pragma unroll
            for (int e = 0; e < 4; e++) acc[mi][ni][e] = 0.f;

    const int NCHUNK = K / G_BK;

    float4 ra[4], rb[4];
    ldg_tile(Atile, K, 0, tid, ra);
    ldg_tile(Btile, K, 0, tid, rb);
    {
        float* base = sm;
        if (SPLIT_A) {
            sts_split(ra, base, base + G_PLANE, tid);
            sts_round(rb, base + 2 * G_PLANE, tid);
        } else {
            sts_round(ra, base, tid);
            sts_round(rb, base + G_PLANE, tid);
        }
    }
    __syncthreads();

    for (int kc = 0; kc < NCHUNK; kc++) {
        int cur = kc & 1;
        if (kc + 1 < NCHUNK) {
            ldg_tile(Atile, K, (kc + 1) * G_BK, tid, ra);
            ldg_tile(Btile, K, (kc + 1) * G_BK, tid, rb);
        }

        const float* Ahi = sm + cur * NPLANES * G_PLANE;
        const float* Alo = Ahi + G_PLANE;                      // valid if SPLIT_A
        const float* Bhi = Ahi + (SPLIT_A ? 2 : 1) * G_PLANE;

#pragma unroll
        for (int ks = 0; ks < 4; ks++) {
            int kk = ks * 8;
            float Ah[4][4], Al[4][4];
#pragma unroll
            for (int mi = 0; mi < 4; mi++) {
                int mrow = wm * 64 + mi * 16 + gid;
                int base = mrow * G_SK + kk + tig;
                Ah[mi][0] = Ahi[base];
                Ah[mi][1] = Ahi[base + 8 * G_SK];
                Ah[mi][2] = Ahi[base + 4];
                Ah[mi][3] = Ahi[base + 8 * G_SK + 4];
                if (SPLIT_A) {
                    Al[mi][0] = Alo[base];
                    Al[mi][1] = Alo[base + 8 * G_SK];
                    Al[mi][2] = Alo[base + 4];
                    Al[mi][3] = Alo[base + 8 * G_SK + 4];
                }
            }
            float Bh[4][2];
#pragma unroll
            for (int ni = 0; ni < 4; ni++) {
                int ncol = wn * 32 + ni * 8 + gid;
                int base = ncol * G_SK + kk + tig;
                Bh[ni][0] = Bhi[base];
                Bh[ni][1] = Bhi[base + 4];
            }
#pragma unroll
            for (int mi = 0; mi < 4; mi++)
#pragma unroll
                for (int ni = 0; ni < 4; ni++) {
                    mma_tf32(acc[mi][ni], Ah[mi][0], Ah[mi][1], Ah[mi][2], Ah[mi][3],
                             Bh[ni][0], Bh[ni][1]);
                    if (SPLIT_A)
                        mma_tf32(acc[mi][ni], Al[mi][0], Al[mi][1], Al[mi][2], Al[mi][3],
                                 Bh[ni][0], Bh[ni][1]);
                }
        }

        if (kc + 1 < NCHUNK) {
            float* base = sm + (1 - cur) * NPLANES * G_PLANE;
            if (SPLIT_A) {
                sts_split(ra, base, base + G_PLANE, tid);
                sts_round(rb, base + 2 * G_PLANE, tid);
            } else {
                sts_round(ra, base, tid);
                sts_round(rb, base + G_PLANE, tid);
            }
        }
        __syncthreads();
    }

#pragma unroll
    for (int mi = 0; mi < 4; mi++) {
        int row0 = blockIdx.y * G_BM + wm * 64 + mi * 16 + gid;
#pragma unroll
        for (int ni = 0; ni < 4; ni++) {
            int col = blockIdx.x * G_BN + wn * 32 + ni * 8 + 2 * tig;
            float* d0 = Cm + (size_t)row0 * N + col;
            float* d1 = Cm + (size_t)(row0 + 8) * N + col;
            float2 v0 = make_float2(acc[mi][ni][0], acc[mi][ni][1]);
            float2 v1 = make_float2(acc[mi][ni][2], acc[mi][ni][3]);
            if (Res) {
                const float2 r0 = *reinterpret_cast<const float2*>(Res + (size_t)row0 * N + col);
                const float2 r1 = *reinterpret_cast<const float2*>(Res + (size_t)(row0 + 8) * N + col);
                v0.x += r0.x; v0.y += r0.y;
                v1.x += r1.x; v1.y += r1.y;
            }
            *reinterpret_cast<float2*>(d0) = v0;
            *reinterpret_cast<float2*>(d1) = v1;
        }
    }
}

// ---------------- RMSNorm ----------------------------------------------------
__global__ void rmsnorm_kernel(const float* __restrict__ x,
                               const float* __restrict__ w,
                               float* __restrict__ out)
{
    int row = blockIdx.x;
    const float4* xr = reinterpret_cast<const float4*>(x + (size_t)row * C_DIM);
    float ss = 0.f;
    for (int i = threadIdx.x; i < C_DIM / 4; i += blockDim.x) {
        float4 v = xr[i];
        ss += v.x * v.x + v.y * v.y + v.z * v.z + v.w * v.w;
    }
#pragma unroll
    for (int o = 16; o; o >>= 1) ss += __shfl_xor_sync(0xffffffffu, ss, o);

    __shared__ float red[8];
    __shared__ float s_inv;
    if ((threadIdx.x & 31) == 0) red[threadIdx.x >> 5] = ss;
    __syncthreads();
    if (threadIdx.x == 0) {
        float tot = 0.f;
        int nw = blockDim.x >> 5;
        for (int i = 0; i < nw; i++) tot += red[i];
        s_inv = rsqrtf(tot * (1.0f / C_DIM) + 1e-6f);
    }
    __syncthreads();
    float inv = s_inv;
    const float4* wr = reinterpret_cast<const float4*>(w);
    float4* outr = reinterpret_cast<float4*>(out + (size_t)row * C_DIM);
    for (int i = threadIdx.x; i < C_DIM / 4; i += blockDim.x) {
        float4 v = xr[i], ww = wr[i];
        v.x = v.x * inv * ww.x;
        v.y = v.y * inv * ww.y;
        v.z = v.z * inv * ww.z;
        v.w = v.w * inv * ww.w;
        outr[i] = v;
    }
}

// ---------------- RoPE (applied to q and k in place) -------------------------
__global__ void rope_kernel(float* __restrict__ q, float* __restrict__ k)
{
    int idx = blockIdx.x * blockDim.x + threadIdx.x;
    if (idx >= T_SEQ * NHEADS * 32) return;
    int i = idx & 31;
    int h = (idx >> 5) & (NHEADS - 1);
    int t = idx >> 9;
    float freq = powf(10000.0f, -(float)(2 * i) * (1.0f / 64.0f));
    float f = (float)t * freq;
    float s, c;
    sincosf(f, &s, &c);
    int base = t * C_DIM + h * HDIM;
    float q1 = q[base + i], q2 = q[base + i + 32];
    q[base + i]      = q1 * c - q2 * s;
    q[base + i + 32] = q2 * c + q1 * s;
    float k1 = k[base + i], k2 = k[base + i + 32];
    k[base + i]      = k1 * c - k2 * s;
    k[base + i + 32] = k2 * c + k1 * s;
}

// ---------------- Flash attention on tensor cores ----------------------------
// Br=Bc=64, 4 warps; warp w owns rows [w*16, w*16+16).
// 1-term QK^T; 4 smem planes -> 70656 B/CTA -> 3 CTAs/SM.
#define FQ_STR 68
#define FV_STR 72
#define F_SMEM_BYTES ((3 * 64 * FQ_STR + 64 * FV_STR) * 4)   // 70656

__global__ __launch_bounds__(128, 3)
void flash_mma_kernel(const float* __restrict__ Qg, const float* __restrict__ Kg,
                      const float* __restrict__ Vg, float* __restrict__ Og)
{
    extern __shared__ float sm[];
    float* Qs = sm;
    float* Kh = Qs + 64 * FQ_STR;
    float* Ps = Kh + 64 * FQ_STR;
    float* Vs = Ps + 64 * FQ_STR;

    int qt = (gridDim.x - 1) - blockIdx.x;   // heavy tiles first
    int h  = blockIdx.y;
    int tid = threadIdx.x;
    int wid = tid >> 5;
    int lane = tid & 31;
    int gid = lane >> 2;
    int tig = lane & 3;
    int wr0 = wid * 16;

#pragma unroll
    for (int v = 0; v < 8; v++) {
        int i = tid + v * 128;
        int row = i >> 4;
        int c4 = i & 15;
        float4 q4 = *reinterpret_cast<const float4*>(
            Qg + (size_t)(qt * 64 + row) * C_DIM + h * HDIM + c4 * 4);
        q4.x = to_tf32(q4.x * 0.125f);
        q4.y = to_tf32(q4.y * 0.125f);
        q4.z = to_tf32(q4.z * 0.125f);
        q4.w = to_tf32(q4.w * 0.125f);
        *reinterpret_cast<float4*>(Qs + row * FQ_STR + c4 * 4) = q4;
    }

    float oacc[8][4];
#pragma unroll
    for (int ni = 0; ni < 8; ni++)
#pragma unroll
        for (int e = 0; e < 4; e++) oacc[ni][e] = 0.f;
    float m0 = -INFINITY, m1 = -INFINITY;
    float l0 = 0.f, l1 = 0.f;

    for (int j = 0; j <= qt; j++) {
        __syncthreads();

#pragma unroll
        for (int v = 0; v < 8; v++) {
            int i = tid + v * 128;
            int row = i >> 4;
            int c4 = i & 15;
            float4 k4 = *reinterpret_cast<const float4*>(
                Kg + (size_t)(j * 64 + row) * C_DIM + h * HDIM + c4 * 4);
            k4.x = to_tf32(k4.x); k4.y = to_tf32(k4.y);
            k4.z = to_tf32(k4.z); k4.w = to_tf32(k4.w);
            *reinterpret_cast<float4*>(Kh + row * FQ_STR + c4 * 4) = k4;
            float4 v4 = *reinterpret_cast<const float4*>(
                Vg + (size_t)(j * 64 + row) * C_DIM + h * HDIM + c4 * 4);
            v4.x = to_tf32(v4.x); v4.y = to_tf32(v4.y);
            v4.z = to_tf32(v4.z); v4.w = to_tf32(v4.w);
            *reinterpret_cast<float4*>(Vs + row * FV_STR + c4 * 4) = v4;
        }
        __syncthreads();

        float sacc[8][4];
#pragma unroll
        for (int ni = 0; ni < 8; ni++)
#pragma unroll
            for (int e = 0; e < 4; e++) sacc[ni][e] = 0.f;

#pragma unroll
        for (int kk = 0; kk < 8; kk++) {
            int kb = kk * 8;
            int abase = (wr0 + gid) * FQ_STR + kb + tig;
            float q0 = Qs[abase];
            float q1 = Qs[abase + 8 * FQ_STR];
            float q2 = Qs[abase + 4];
            float q3 = Qs[abase + 8 * FQ_STR + 4];
#pragma unroll
            for (int ni = 0; ni < 8; ni++) {
                int bbase = (ni * 8 + gid) * FQ_STR + kb + tig;
                float b0 = Kh[bbase];
                float b1 = Kh[bbase + 4];
                mma_tf32(sacc[ni], q0, q1, q2, q3, b0, b1);
            }
        }

        if (j == qt) {
#pragma unroll
            for (int ni = 0; ni < 8; ni++) {
                int c0 = ni * 8 + 2 * tig;
                int rA = wr0 + gid, rB = wr0 + gid + 8;
                if (c0 > rA)     sacc[ni][0] = -INFINITY;
                if (c0 + 1 > rA) sacc[ni][1] = -INFINITY;
                if (c0 > rB)     sacc[ni][2] = -INFINITY;
                if (c0 + 1 > rB) sacc[ni][3] = -INFINITY;
            }
        }

        float rm0 = -INFINITY, rm1 = -INFINITY;
#pragma unroll
        for (int ni = 0; ni < 8; ni++) {
            rm0 = fmaxf(rm0, fmaxf(sacc[ni][0], sacc[ni][1]));
            rm1 = fmaxf(rm1, fmaxf(sacc[ni][2], sacc[ni][3]));
        }
        rm0 = fmaxf(rm0, __shfl_xor_sync(0xffffffffu, rm0, 1));
        rm0 = fmaxf(rm0, __shfl_xor_sync(0xffffffffu, rm0, 2));
        rm1 = fmaxf(rm1, __shfl_xor_sync(0xffffffffu, rm1, 1));
        rm1 = fmaxf(rm1, __shfl_xor_sync(0xffffffffu, rm1, 2));

        float mn0 = fmaxf(m0, rm0);
        float mn1 = fmaxf(m1, rm1);
        float alpha0 = __expf(m0 - mn0);
        float alpha1 = __expf(m1 - mn1);
        m0 = mn0; m1 = mn1;

        float rs0 = 0.f, rs1 = 0.f;
#pragma unroll
        for (int ni = 0; ni < 8; ni++) {
            float p0 = __expf(sacc[ni][0] - mn0);
            float p1 = __expf(sacc[ni][1] - mn0);
            float p2 = __expf(sacc[ni][2] - mn1);
            float p3 = __expf(sacc[ni][3] - mn1);
            rs0 += p0 + p1;
            rs1 += p2 + p3;
            int c0 = ni * 8 + 2 * tig;
            *reinterpret_cast<float2*>(Ps + (wr0 + gid) * FQ_STR + c0) =
                make_float2(to_tf32(p0), to_tf32(p1));
            *reinterpret_cast<float2*>(Ps + (wr0 + gid + 8) * FQ_STR + c0) =
                make_float2(to_tf32(p2), to_tf32(p3));
        }
        rs0 += __shfl_xor_sync(0xffffffffu, rs0, 1);
        rs0 += __shfl_xor_sync(0xffffffffu, rs0, 2);
        rs1 += __shfl_xor_sync(0xffffffffu, rs1, 1);
        rs1 += __shfl_xor_sync(0xffffffffu, rs1, 2);
        l0 = l0 * alpha0 + rs0;
        l1 = l1 * alpha1 + rs1;

#pragma unroll
        for (int ni = 0; ni < 8; ni++) {
            oacc[ni][0] *= alpha0; oacc[ni][1] *= alpha0;
            oacc[ni][2] *= alpha1; oacc[ni][3] *= alpha1;
        }
        __syncwarp();

#pragma unroll
        for (int kk = 0; kk < 8; kk++) {
            int kb = kk * 8;
            int abase = (wr0 + gid) * FQ_STR + kb + tig;
            float a0 = Ps[abase];
            float a1 = Ps[abase + 8 * FQ_STR];
            float a2 = Ps[abase + 4];
            float a3 = Ps[abase + 8 * FQ_STR + 4];
#pragma unroll
            for (int ni = 0; ni < 8; ni++) {
                float b0 = Vs[(kb + tig) * FV_STR + ni * 8 + gid];
                float b1 = Vs[(kb + tig + 4) * FV_STR + ni * 8 + gid];
                mma_tf32(oacc[ni], a0, a1, a2, a3, b0, b1);
            }
        }
    }

    float invl0 = 1.f / l0;
    float invl1 = 1.f / l1;
    int row0 = qt * 64 + wr0 + gid;
    int row1 = row0 + 8;
#pragma unroll
    for (int ni = 0; ni < 8; ni++) {
        int col = h * HDIM + ni * 8 + 2 * tig;
        *reinterpret_cast<float2*>(Og + (size_t)row0 * C_DIM + col) =
            make_float2(oacc[ni][0] * invl0, oacc[ni][1] * invl0);
        *reinterpret_cast<float2*>(Og + (size_t)row1 * C_DIM + col) =
            make_float2(oacc[ni][2] * invl1, oacc[ni][3] * invl1);
    }
}

// ---------------- launch -----------------------------------------------------
extern "C" void kernel_launch(void* const* d_in, const int* in_sizes, int n_in,
                              void* d_out, int out_size)
{
    const float* x      = (const float*)d_in[0];
    const float* wq     = (const float*)d_in[1];
    const float* wk     = (const float*)d_in[2];
    const float* wv     = (const float*)d_in[3];
    const float* wo     = (const float*)d_in[4];
    const float* norm_w = (const float*)d_in[5];
    float* out = (float*)d_out;

    float *normed, *q, *k, *v, *att;
    cudaGetSymbolAddress((void**)&normed, g_normed);
    cudaGetSymbolAddress((void**)&q,      g_q);
    cudaGetSymbolAddress((void**)&k,      g_k);
    cudaGetSymbolAddress((void**)&v,      g_v);
    cudaGetSymbolAddress((void**)&att,    g_att);

    // 1) RMSNorm
    rmsnorm_kernel<<<T_SEQ, 256>>>(x, norm_w, normed);

    // 2) Q/K/V projections: 1-term pure tf32 (errors diluted through attention)
    cudaFuncSetAttribute(gemm_mma_kernel<false>,
                         cudaFuncAttributeMaxDynamicSharedMemorySize, G_SMEM_1T);
    cudaFuncSetAttribute(gemm_mma_kernel<true>,
                         cudaFuncAttributeMaxDynamicSharedMemorySize, G_SMEM_2T);
    dim3 gdim(C_DIM / G_BN, T_SEQ / G_BM);
    gemm_mma_kernel<false><<<gdim, 256, G_SMEM_1T>>>(normed, wq, nullptr, q, T_SEQ, C_DIM, C_DIM);
    gemm_mma_kernel<false><<<gdim, 256, G_SMEM_1T>>>(normed, wk, nullptr, k, T_SEQ, C_DIM, C_DIM);
    gemm_mma_kernel<false><<<gdim, 256, G_SMEM_1T>>>(normed, wv, nullptr, v, T_SEQ, C_DIM, C_DIM);

    // 3) RoPE on q,k
    int nrope = T_SEQ * NHEADS * 32;
    rope_kernel<<<(nrope + 255) / 256, 256>>>(q, k);

    // 4) causal flash attention on tensor cores (1-term QK, occ=3)
    cudaFuncSetAttribute(flash_mma_kernel, cudaFuncAttributeMaxDynamicSharedMemorySize,
                         F_SMEM_BYTES);
    dim3 fgrid(T_SEQ / 64, NHEADS);
    flash_mma_kernel<<<fgrid, 128, F_SMEM_BYTES>>>(q, k, v, att);

    // 5) output projection + residual: 2-term (error path is direct)
    gemm_mma_kernel<true><<<gdim, 256, G_SMEM_2T>>>(att, wo, x, out, T_SEQ, C_DIM, C_DIM);
}

// round 11
// speedup vs baseline: 1.3334x; 1.0233x over previous
#include <cuda_runtime.h>
#include <math.h>
#include <stdint.h>

#define T_SEQ   4096
#define C_DIM   1024
#define NHEADS  16
#define HDIM    64

// ---------------- scratch (static device globals; no allocation) -------------
__device__ float g_normed[T_SEQ * C_DIM];
__device__ float g_q[T_SEQ * C_DIM];
__device__ float g_k[T_SEQ * C_DIM];
__device__ float g_v[T_SEQ * C_DIM];
__device__ float g_att[T_SEQ * C_DIM];

// ================= tf32 helpers ==============================================
__device__ __forceinline__ void split_tf32(float a, float& hi, float& lo)
{
    uint32_t h;
    asm("cvt.rna.tf32.f32 %0, %1;" : "=r"(h) : "f"(a));
    hi = __uint_as_float(h);
    float r = a - hi;
    uint32_t l2;
    asm("cvt.rna.tf32.f32 %0, %1;" : "=r"(l2) : "f"(r));
    lo = __uint_as_float(l2);
}

__device__ __forceinline__ float to_tf32(float a)
{
    uint32_t u;
    asm("cvt.rna.tf32.f32 %0, %1;" : "=r"(u) : "f"(a));
    return __uint_as_float(u);
}

// m16n8k8 tf32 mma (sm_80+ baseline PTX, runs on tensor pipe)
__device__ __forceinline__ void mma_tf32(float d[4],
                                         float a0, float a1, float a2, float a3,
                                         float b0, float b1)
{
    asm volatile(
        "mma.sync.aligned.m16n8k8.row.col.f32.tf32.tf32.f32 "
        "{%0,%1,%2,%3}, {%4,%5,%6,%7}, {%8,%9}, {%0,%1,%2,%3};"
        : "+f"(d[0]), "+f"(d[1]), "+f"(d[2]), "+f"(d[3])
        : "r"(__float_as_uint(a0)), "r"(__float_as_uint(a1)),
          "r"(__float_as_uint(a2)), "r"(__float_as_uint(a3)),
          "r"(__float_as_uint(b0)), "r"(__float_as_uint(b1)));
}

// ================= HMMA tf32 GEMM: C[M,N] = A[M,K] @ B[N,K]^T (+Res) =========
// SPLIT_A=true : 2-term Ahi*Bhi + Alo*Bhi (3 smem planes).
// SPLIT_A=false: 1-term pure tf32 (2 smem planes).
#define G_BM 128
#define G_BN 128
#define G_BK 32
#define G_SK 36
#define G_PLANE (128 * G_SK)
#define G_SMEM_2T (2 * 3 * G_PLANE * 4)   // 110592 bytes
#define G_SMEM_1T (2 * 2 * G_PLANE * 4)   //  73728 bytes

__device__ __forceinline__ void ldg_tile(const float* __restrict__ G, int ldk,
                                         int k0, int tid, float4 r[4])
{
#pragma unroll
    for (int v = 0; v < 4; v++) {
        int i = tid + v * 256;
        int row = i >> 3;
        int c4 = i & 7;
        r[v] = *reinterpret_cast<const float4*>(G + (size_t)row * ldk + k0 + c4 * 4);
    }
}

__device__ __forceinline__ void sts_split(const float4 r[4], float* __restrict__ hi,
                                          float* __restrict__ lo, int tid)
{
#pragma unroll
    for (int v = 0; v < 4; v++) {
        int i = tid + v * 256;
        int row = i >> 3;
        int c4 = i & 7;
        int off = row * G_SK + c4 * 4;
        float4 h4, l4;
        split_tf32(r[v].x, h4.x, l4.x);
        split_tf32(r[v].y, h4.y, l4.y);
        split_tf32(r[v].z, h4.z, l4.z);
        split_tf32(r[v].w, h4.w, l4.w);
        *reinterpret_cast<float4*>(hi + off) = h4;
        *reinterpret_cast<float4*>(lo + off) = l4;
    }
}

__device__ __forceinline__ void sts_round(const float4 r[4], float* __restrict__ hi,
                                          int tid)
{
#pragma unroll
    for (int v = 0; v < 4; v++) {
        int i = tid + v * 256;
        int row = i >> 3;
        int c4 = i & 7;
        int off = row * G_SK + c4 * 4;
        float4 h4;
        h4.x = to_tf32(r[v].x);
        h4.y = to_tf32(r[v].y);
        h4.z = to_tf32(r[v].z);
        h4.w = to_tf32(r[v].w);
        *reinterpret_cast<float4*>(hi + off) = h4;
    }
}

template <bool SPLIT_A>
__global__ __launch_bounds__(256, 1)
void gemm_mma_kernel(const float* __restrict__ A, const float* __restrict__ B,
                     const float* __restrict__ Res, float* __restrict__ Cm,
                     int M, int N, int K)
{
    extern __shared__ float sm[];
    const int NPLANES = SPLIT_A ? 3 : 2;
    int tid = threadIdx.x;
    int wid = tid >> 5;
    int lane = tid & 31;
    int gid = lane >> 2;
    int tig = lane & 3;
    int wm = wid & 1;
    int wn = wid >> 1;

    const float* Atile = A + (size_t)(blockIdx.y * G_BM) * K;
    const float* Btile = B + (size_t)(blockIdx.x * G_BN) * K;

    float acc[4][4][4];
#pragma unroll
    for (int mi = 0; mi < 4; mi++)
#pragma unroll
        for (int ni = 0; ni < 4; ni++)
#pragma unroll
            for (int e = 0; e < 4; e++) acc[mi][ni][e] = 0.f;

    const int NCHUNK = K / G_BK;

    float4 ra[4], rb[4];
    ldg_tile(Atile, K, 0, tid, ra);
    ldg_tile(Btile, K, 0, tid, rb);
    {
        float* base = sm;
        if (SPLIT_A) {
            sts_split(ra, base, base + G_PLANE, tid);
            sts_round(rb, base + 2 * G_PLANE, tid);
        } else {
            sts_round(ra, base, tid);
            sts_round(rb, base + G_PLANE, tid);
        }
    }
    __syncthreads();

    for (int kc = 0; kc < NCHUNK; kc++) {
        int cur = kc & 1;
        if (kc + 1 < NCHUNK) {
            ldg_tile(Atile, K, (kc + 1) * G_BK, tid, ra);
            ldg_tile(Btile, K, (kc + 1) * G_BK, tid, rb);
        }

        const float* Ahi = sm + cur * NPLANES * G_PLANE;
        const float* Alo = Ahi + G_PLANE;
        const float* Bhi = Ahi + (SPLIT_A ? 2 : 1) * G_PLANE;

#pragma unroll
        for (int ks = 0; ks < 4; ks++) {
            int kk = ks * 8;
            float Ah[4][4], Al[4][4];
#pragma unroll
            for (int mi = 0; mi < 4; mi++) {
                int mrow = wm * 64 + mi * 16 + gid;
                int base = mrow * G_SK + kk + tig;
                Ah[mi][0] = Ahi[base];
                Ah[mi][1] = Ahi[base + 8 * G_SK];
                Ah[mi][2] = Ahi[base + 4];
                Ah[mi][3] = Ahi[base + 8 * G_SK + 4];
                if (SPLIT_A) {
                    Al[mi][0] = Alo[base];
                    Al[mi][1] = Alo[base + 8 * G_SK];
                    Al[mi][2] = Alo[base + 4];
                    Al[mi][3] = Alo[base + 8 * G_SK + 4];
                }
            }
            float Bh[4][2];
#pragma unroll
            for (int ni = 0; ni < 4; ni++) {
                int ncol = wn * 32 + ni * 8 + gid;
                int base = ncol * G_SK + kk + tig;
                Bh[ni][0] = Bhi[base];
                Bh[ni][1] = Bhi[base + 4];
            }
#pragma unroll
            for (int mi = 0; mi < 4; mi++)
#pragma unroll
                for (int ni = 0; ni < 4; ni++) {
                    mma_tf32(acc[mi][ni], Ah[mi][0], Ah[mi][1], Ah[mi][2], Ah[mi][3],
                             Bh[ni][0], Bh[ni][1]);
                    if (SPLIT_A)
                        mma_tf32(acc[mi][ni], Al[mi][0], Al[mi][1], Al[mi][2], Al[mi][3],
                                 Bh[ni][0], Bh[ni][1]);
                }
        }

        if (kc + 1 < NCHUNK) {
            float* base = sm + (1 - cur) * NPLANES * G_PLANE;
            if (SPLIT_A) {
                sts_split(ra, base, base + G_PLANE, tid);
                sts_round(rb, base + 2 * G_PLANE, tid);
            } else {
                sts_round(ra, base, tid);
                sts_round(rb, base + G_PLANE, tid);
            }
        }
        __syncthreads();
    }

#pragma unroll
    for (int mi = 0; mi < 4; mi++) {
        int row0 = blockIdx.y * G_BM + wm * 64 + mi * 16 + gid;
#pragma unroll
        for (int ni = 0; ni < 4; ni++) {
            int col = blockIdx.x * G_BN + wn * 32 + ni * 8 + 2 * tig;
            float* d0 = Cm + (size_t)row0 * N + col;
            float* d1 = Cm + (size_t)(row0 + 8) * N + col;
            float2 v0 = make_float2(acc[mi][ni][0], acc[mi][ni][1]);
            float2 v1 = make_float2(acc[mi][ni][2], acc[mi][ni][3]);
            if (Res) {
                const float2 r0 = *reinterpret_cast<const float2*>(Res + (size_t)row0 * N + col);
                const float2 r1 = *reinterpret_cast<const float2*>(Res + (size_t)(row0 + 8) * N + col);
                v0.x += r0.x; v0.y += r0.y;
                v1.x += r1.x; v1.y += r1.y;
            }
            *reinterpret_cast<float2*>(d0) = v0;
            *reinterpret_cast<float2*>(d1) = v1;
        }
    }
}

// ---------------- RMSNorm ----------------------------------------------------
__global__ void rmsnorm_kernel(const float* __restrict__ x,
                               const float* __restrict__ w,
                               float* __restrict__ out)
{
    int row = blockIdx.x;
    const float4* xr = reinterpret_cast<const float4*>(x + (size_t)row * C_DIM);
    float ss = 0.f;
    for (int i = threadIdx.x; i < C_DIM / 4; i += blockDim.x) {
        float4 v = xr[i];
        ss += v.x * v.x + v.y * v.y + v.z * v.z + v.w * v.w;
    }
#pragma unroll
    for (int o = 16; o; o >>= 1) ss += __shfl_xor_sync(0xffffffffu, ss, o);

    __shared__ float red[8];
    __shared__ float s_inv;
    if ((threadIdx.x & 31) == 0) red[threadIdx.x >> 5] = ss;
    __syncthreads();
    if (threadIdx.x == 0) {
        float tot = 0.f;
        int nw = blockDim.x >> 5;
        for (int i = 0; i < nw; i++) tot += red[i];
        s_inv = rsqrtf(tot * (1.0f / C_DIM) + 1e-6f);
    }
    __syncthreads();
    float inv = s_inv;
    const float4* wr = reinterpret_cast<const float4*>(w);
    float4* outr = reinterpret_cast<float4*>(out + (size_t)row * C_DIM);
    for (int i = threadIdx.x; i < C_DIM / 4; i += blockDim.x) {
        float4 v = xr[i], ww = wr[i];
        v.x = v.x * inv * ww.x;
        v.y = v.y * inv * ww.y;
        v.z = v.z * inv * ww.z;
        v.w = v.w * inv * ww.w;
        outr[i] = v;
    }
}

// ---------------- RoPE (applied to q and k in place) -------------------------
__global__ void rope_kernel(float* __restrict__ q, float* __restrict__ k)
{
    int idx = blockIdx.x * blockDim.x + threadIdx.x;
    if (idx >= T_SEQ * NHEADS * 32) return;
    int i = idx & 31;
    int h = (idx >> 5) & (NHEADS - 1);
    int t = idx >> 9;
    float freq = powf(10000.0f, -(float)(2 * i) * (1.0f / 64.0f));
    float f = (float)t * freq;
    float s, c;
    sincosf(f, &s, &c);
    int base = t * C_DIM + h * HDIM;
    float q1 = q[base + i], q2 = q[base + i + 32];
    q[base + i]      = q1 * c - q2 * s;
    q[base + i + 32] = q2 * c + q1 * s;
    float k1 = k[base + i], k2 = k[base + i + 32];
    k[base + i]      = k1 * c - k2 * s;
    k[base + i + 32] = k2 * c + k1 * s;
}

// ---------------- Flash attention on tensor cores ----------------------------
// Br=128, Bc=64, 8 warps (256 thr); warp w owns rows [w*16, w*16+16).
// 1-term tf32 QK^T and PV; K/V tile loads amortized over 128 Q rows.
#define FQ_STR 68
#define FV_STR 72
#define F_SMEM_BYTES ((128 * FQ_STR + 64 * FQ_STR + 128 * FQ_STR + 64 * FV_STR) * 4) // 105472

__global__ __launch_bounds__(256, 2)
void flash_mma_kernel(const float* __restrict__ Qg, const float* __restrict__ Kg,
                      const float* __restrict__ Vg, float* __restrict__ Og)
{
    extern __shared__ float sm[];
    float* Qs = sm;                    // [128][FQ_STR]
    float* Kh = Qs + 128 * FQ_STR;     // [64][FQ_STR]
    float* Ps = Kh + 64 * FQ_STR;      // [128][FQ_STR]
    float* Vs = Ps + 128 * FQ_STR;     // [64][FV_STR]

    int qb = (gridDim.x - 1) - blockIdx.x;   // heavy blocks first
    int h  = blockIdx.y;
    int tid = threadIdx.x;
    int wid = tid >> 5;
    int lane = tid & 31;
    int gid = lane >> 2;
    int tig = lane & 3;
    int wr0 = wid * 16;

    // ---- load Q tile [128 x 64] (scale by 0.125, round to tf32) ----
#pragma unroll
    for (int v = 0; v < 8; v++) {
        int i = tid + v * 256;
        int row = i >> 4;
        int c4 = i & 15;
        float4 q4 = *reinterpret_cast<const float4*>(
            Qg + (size_t)(qb * 128 + row) * C_DIM + h * HDIM + c4 * 4);
        q4.x = to_tf32(q4.x * 0.125f);
        q4.y = to_tf32(q4.y * 0.125f);
        q4.z = to_tf32(q4.z * 0.125f);
        q4.w = to_tf32(q4.w * 0.125f);
        *reinterpret_cast<float4*>(Qs + row * FQ_STR + c4 * 4) = q4;
    }

    float oacc[8][4];
#pragma unroll
    for (int ni = 0; ni < 8; ni++)
#pragma unroll
        for (int e = 0; e < 4; e++) oacc[ni][e] = 0.f;
    float m0 = -INFINITY, m1 = -INFINITY;
    float l0 = 0.f, l1 = 0.f;

    const int ntiles = 2 * qb + 2;

    for (int j = 0; j < ntiles; j++) {
        __syncthreads();   // previous tile's smem reads complete (and Q on iter 0)

        // ---- load K and V tiles [64 x 64] (tf32-rounded) ----
#pragma unroll
        for (int v = 0; v < 4; v++) {
            int i = tid + v * 256;
            int row = i >> 4;
            int c4 = i & 15;
            float4 k4 = *reinterpret_cast<const float4*>(
                Kg + (size_t)(j * 64 + row) * C_DIM + h * HDIM + c4 * 4);
            k4.x = to_tf32(k4.x); k4.y = to_tf32(k4.y);
            k4.z = to_tf32(k4.z); k4.w = to_tf32(k4.w);
            *reinterpret_cast<float4*>(Kh + row * FQ_STR + c4 * 4) = k4;
            float4 v4 = *reinterpret_cast<const float4*>(
                Vg + (size_t)(j * 64 + row) * C_DIM + h * HDIM + c4 * 4);
            v4.x = to_tf32(v4.x); v4.y = to_tf32(v4.y);
            v4.z = to_tf32(v4.z); v4.w = to_tf32(v4.w);
            *reinterpret_cast<float4*>(Vs + row * FV_STR + c4 * 4) = v4;
        }
        __syncthreads();

        // ---- S = Q K^T (single term) ----
        float sacc[8][4];
#pragma unroll
        for (int ni = 0; ni < 8; ni++)
#pragma unroll
            for (int e = 0; e < 4; e++) sacc[ni][e] = 0.f;

#pragma unroll
        for (int kk = 0; kk < 8; kk++) {
            int kb = kk * 8;
            int abase = (wr0 + gid) * FQ_STR + kb + tig;
            float q0 = Qs[abase];
            float q1 = Qs[abase + 8 * FQ_STR];
            float q2 = Qs[abase + 4];
            float q3 = Qs[abase + 8 * FQ_STR + 4];
#pragma unroll
            for (int ni = 0; ni < 8; ni++) {
                int bbase = (ni * 8 + gid) * FQ_STR + kb + tig;
                float b0 = Kh[bbase];
                float b1 = Kh[bbase + 4];
                mma_tf32(sacc[ni], q0, q1, q2, q3, b0, b1);
            }
        }

        // ---- causal mask (last two KV tiles overlap the diagonal) ----
        if (j >= 2 * qb) {
            int growA = qb * 128 + wr0 + gid;
            int growB = growA + 8;
            int gc0 = j * 64;
#pragma unroll
            for (int ni = 0; ni < 8; ni++) {
                int c0 = gc0 + ni * 8 + 2 * tig;
                if (c0 > growA)     sacc[ni][0] = -INFINITY;
                if (c0 + 1 > growA) sacc[ni][1] = -INFINITY;
                if (c0 > growB)     sacc[ni][2] = -INFINITY;
                if (c0 + 1 > growB) sacc[ni][3] = -INFINITY;
            }
        }

        // ---- online softmax ----
        float rm0 = -INFINITY, rm1 = -INFINITY;
#pragma unroll
        for (int ni = 0; ni < 8; ni++) {
            rm0 = fmaxf(rm0, fmaxf(sacc[ni][0], sacc[ni][1]));
            rm1 = fmaxf(rm1, fmaxf(sacc[ni][2], sacc[ni][3]));
        }
        rm0 = fmaxf(rm0, __shfl_xor_sync(0xffffffffu, rm0, 1));
        rm0 = fmaxf(rm0, __shfl_xor_sync(0xffffffffu, rm0, 2));
        rm1 = fmaxf(rm1, __shfl_xor_sync(0xffffffffu, rm1, 1));
        rm1 = fmaxf(rm1, __shfl_xor_sync(0xffffffffu, rm1, 2));

        float mn0 = fmaxf(m0, rm0);
        float mn1 = fmaxf(m1, rm1);
        float alpha0 = __expf(m0 - mn0);
        float alpha1 = __expf(m1 - mn1);
        m0 = mn0; m1 = mn1;

        float rs0 = 0.f, rs1 = 0.f;
#pragma unroll
        for (int ni = 0; ni < 8; ni++) {
            float p0 = __expf(sacc[ni][0] - mn0);
            float p1 = __expf(sacc[ni][1] - mn0);
            float p2 = __expf(sacc[ni][2] - mn1);
            float p3 = __expf(sacc[ni][3] - mn1);
            rs0 += p0 + p1;
            rs1 += p2 + p3;
            int c0 = ni * 8 + 2 * tig;
            *reinterpret_cast<float2*>(Ps + (wr0 + gid) * FQ_STR + c0) =
                make_float2(to_tf32(p0), to_tf32(p1));
            *reinterpret_cast<float2*>(Ps + (wr0 + gid + 8) * FQ_STR + c0) =
                make_float2(to_tf32(p2), to_tf32(p3));
        }
        rs0 += __shfl_xor_sync(0xffffffffu, rs0, 1);
        rs0 += __shfl_xor_sync(0xffffffffu, rs0, 2);
        rs1 += __shfl_xor_sync(0xffffffffu, rs1, 1);
        rs1 += __shfl_xor_sync(0xffffffffu, rs1, 2);
        l0 = l0 * alpha0 + rs0;
        l1 = l1 * alpha1 + rs1;

#pragma unroll
        for (int ni = 0; ni < 8; ni++) {
            oacc[ni][0] *= alpha0; oacc[ni][1] *= alpha0;
            oacc[ni][2] *= alpha1; oacc[ni][3] *= alpha1;
        }
        __syncwarp();   // this warp's Ps rows visible warp-wide

        // ---- O += P V ----
#pragma unroll
        for (int kk = 0; kk < 8; kk++) {
            int kb = kk * 8;
            int abase = (wr0 + gid) * FQ_STR + kb + tig;
            float a0 = Ps[abase];
            float a1 = Ps[abase + 8 * FQ_STR];
            float a2 = Ps[abase + 4];
            float a3 = Ps[abase + 8 * FQ_STR + 4];
#pragma unroll
            for (int ni = 0; ni < 8; ni++) {
                float b0 = Vs[(kb + tig) * FV_STR + ni * 8 + gid];
                float b1 = Vs[(kb + tig + 4) * FV_STR + ni * 8 + gid];
                mma_tf32(oacc[ni], a0, a1, a2, a3, b0, b1);
            }
        }
    }

    float invl0 = 1.f / l0;
    float invl1 = 1.f / l1;
    int row0 = qb * 128 + wr0 + gid;
    int row1 = row0 + 8;
#pragma unroll
    for (int ni = 0; ni < 8; ni++) {
        int col = h * HDIM + ni * 8 + 2 * tig;
        *reinterpret_cast<float2*>(Og + (size_t)row0 * C_DIM + col) =
            make_float2(oacc[ni][0] * invl0, oacc[ni][1] * invl0);
        *reinterpret_cast<float2*>(Og + (size_t)row1 * C_DIM + col) =
            make_float2(oacc[ni][2] * invl1, oacc[ni][3] * invl1);
    }
}

// ---------------- launch -----------------------------------------------------
extern "C" void kernel_launch(void* const* d_in, const int* in_sizes, int n_in,
                              void* d_out, int out_size)
{
    const float* x      = (const float*)d_in[0];
    const float* wq     = (const float*)d_in[1];
    const float* wk     = (const float*)d_in[2];
    const float* wv     = (const float*)d_in[3];
    const float* wo     = (const float*)d_in[4];
    const float* norm_w = (const float*)d_in[5];
    float* out = (float*)d_out;

    float *normed, *q, *k, *v, *att;
    cudaGetSymbolAddress((void**)&normed, g_normed);
    cudaGetSymbolAddress((void**)&q,      g_q);
    cudaGetSymbolAddress((void**)&k,      g_k);
    cudaGetSymbolAddress((void**)&v,      g_v);
    cudaGetSymbolAddress((void**)&att,    g_att);

    // 1) RMSNorm
    rmsnorm_kernel<<<T_SEQ, 256>>>(x, norm_w, normed);

    // 2) Q/K/V projections: 1-term pure tf32
    cudaFuncSetAttribute(gemm_mma_kernel<false>,
                         cudaFuncAttributeMaxDynamicSharedMemorySize, G_SMEM_1T);
    dim3 gdim(C_DIM / G_BN, T_SEQ / G_BM);
    gemm_mma_kernel<false><<<gdim, 256, G_SMEM_1T>>>(normed, wq, nullptr, q, T_SEQ, C_DIM, C_DIM);
    gemm_mma_kernel<false><<<gdim, 256, G_SMEM_1T>>>(normed, wk, nullptr, k, T_SEQ, C_DIM, C_DIM);
    gemm_mma_kernel<false><<<gdim, 256, G_SMEM_1T>>>(normed, wv, nullptr, v, T_SEQ, C_DIM, C_DIM);

    // 3) RoPE on q,k
    int nrope = T_SEQ * NHEADS * 32;
    rope_kernel<<<(nrope + 255) / 256, 256>>>(q, k);

    // 4) causal flash attention, Br=128
    cudaFuncSetAttribute(flash_mma_kernel, cudaFuncAttributeMaxDynamicSharedMemorySize,
                         F_SMEM_BYTES);
    dim3 fgrid(T_SEQ / 128, NHEADS);
    flash_mma_kernel<<<fgrid, 256, F_SMEM_BYTES>>>(q, k, v, att);

    // 5) output projection + residual: 1-term tf32 (error diluted by residual)
    gemm_mma_kernel<false><<<gdim, 256, G_SMEM_1T>>>(att, wo, x, out, T_SEQ, C_DIM, C_DIM);
}

// round 12
// speedup vs baseline: 1.4940x; 1.1205x over previous
#include <cuda_runtime.h>
#include <math.h>
#include <stdint.h>

#define T_SEQ   4096
#define C_DIM   1024
#define NHEADS  16
#define HDIM    64

// ---------------- scratch (static device globals; no allocation) -------------
__device__ float g_normed[T_SEQ * C_DIM];
__device__ float g_q[T_SEQ * C_DIM];
__device__ float g_k[T_SEQ * C_DIM];
__device__ float g_v[T_SEQ * C_DIM];
__device__ float g_att[T_SEQ * C_DIM];
__device__ float g_wr[4][C_DIM * C_DIM];   // tf32-rounded weights

// ================= helpers ===================================================
__device__ __forceinline__ uint32_t smem_u32(const void* p) {
    uint32_t a;
    asm("{ .reg .u64 t; cvta.to.shared.u64 t, %1; cvt.u32.u64 %0, t; }"
        : "=r"(a) : "l"(p));
    return a;
}

__device__ __forceinline__ void cp_async16(uint32_t saddr, const void* gptr) {
    asm volatile("cp.async.cg.shared.global [%0], [%1], 16;"
                 :: "r"(saddr), "l"(gptr));
}
__device__ __forceinline__ void cp_commit() {
    asm volatile("cp.async.commit_group;");
}
template <int N>
__device__ __forceinline__ void cp_wait() {
    asm volatile("cp.async.wait_group %0;" :: "n"(N));
}

__device__ __forceinline__ float to_tf32(float a)
{
    uint32_t u;
    asm("cvt.rna.tf32.f32 %0, %1;" : "=r"(u) : "f"(a));
    return __uint_as_float(u);
}

// m16n8k8 tf32 mma (sm_80+ baseline PTX, runs on tensor pipe)
__device__ __forceinline__ void mma_tf32(float d[4],
                                         float a0, float a1, float a2, float a3,
                                         float b0, float b1)
{
    asm volatile(
        "mma.sync.aligned.m16n8k8.row.col.f32.tf32.tf32.f32 "
        "{%0,%1,%2,%3}, {%4,%5,%6,%7}, {%8,%9}, {%0,%1,%2,%3};"
        : "+f"(d[0]), "+f"(d[1]), "+f"(d[2]), "+f"(d[3])
        : "r"(__float_as_uint(a0)), "r"(__float_as_uint(a1)),
          "r"(__float_as_uint(a2)), "r"(__float_as_uint(a3)),
          "r"(__float_as_uint(b0)), "r"(__float_as_uint(b1)));
}

// ---------------- elementwise tf32 rounding (weights prepass) ----------------
__global__ void round_tf32_kernel(const float* __restrict__ in,
                                  float* __restrict__ out, int n4)
{
    int i = blockIdx.x * blockDim.x + threadIdx.x;
    if (i >= n4) return;
    float4 v = reinterpret_cast<const float4*>(in)[i];
    v.x = to_tf32(v.x); v.y = to_tf32(v.y);
    v.z = to_tf32(v.z); v.w = to_tf32(v.w);
    reinterpret_cast<float4*>(out)[i] = v;
}

// ================= HMMA tf32 GEMM: C[M,N] = A[M,K] @ B[N,K]^T (+Res) =========
// Inputs are PRE-ROUNDED to tf32 — kernel is a pure copy+mma pipeline.
// 128x128 CTA tile, BK=32, 8 warps (2x4), warp tile 64x32, cp.async staging,
// occ=2 -> grid 256 runs in a single wave (296 slots).
#define G_BM 128
#define G_BN 128
#define G_BK 32
#define G_SK 36
#define G_PLANE (128 * G_SK)
#define G_STAGE (2 * G_PLANE)                 // A + B planes
#define G_SMEM_TOTAL (2 * G_STAGE * 4)        // 73728 bytes

__device__ __forceinline__ void issue_tile(uint32_t s_a, uint32_t s_b,
                                           const float* __restrict__ Ag,
                                           const float* __restrict__ Bg,
                                           int K, int k0, int tid)
{
#pragma unroll
    for (int t = 0; t < 4; t++) {
        int idx = tid + t * 256;          // 1024 float4 per 128x32 tile
        int row = idx >> 3;               // 8 float4 per 32-float row
        int c4 = idx & 7;
        uint32_t soff = (uint32_t)(row * G_SK + c4 * 4) * 4u;
        cp_async16(s_a + soff, Ag + (size_t)row * K + k0 + c4 * 4);
        cp_async16(s_b + soff, Bg + (size_t)row * K + k0 + c4 * 4);
    }
}

__global__ __launch_bounds__(256, 2)
void gemm_mma_kernel(const float* __restrict__ A, const float* __restrict__ B,
                     const float* __restrict__ Res, float* __restrict__ Cm,
                     int M, int N, int K)
{
    extern __shared__ float sm[];
    uint32_t smem_base = smem_u32(sm);
    int tid = threadIdx.x;
    int wid = tid >> 5;
    int lane = tid & 31;
    int gid = lane >> 2;
    int tig = lane & 3;
    int wm = wid & 1;          // 2 m-slabs of 64
    int wn = wid >> 1;         // 4 n-slabs of 32

    const float* Atile = A + (size_t)(blockIdx.y * G_BM) * K;
    const float* Btile = B + (size_t)(blockIdx.x * G_BN) * K;

    float acc[4][4][4];
#pragma unroll
    for (int mi = 0; mi < 4; mi++)
#pragma unroll
        for (int ni = 0; ni < 4; ni++)
#pragma unroll
            for (int e = 0; e < 4; e++) acc[mi][ni][e] = 0.f;

    const int NCHUNK = K / G_BK;   // 32

    // prologue: chunk 0 -> stage 0
    issue_tile(smem_base, smem_base + G_PLANE * 4u, Atile, Btile, K, 0, tid);
    cp_commit();

    for (int kc = 0; kc < NCHUNK; kc++) {
        int cur = kc & 1;
        if (kc + 1 < NCHUNK) {
            uint32_t sb = smem_base + (uint32_t)(1 - cur) * G_STAGE * 4u;
            issue_tile(sb, sb + G_PLANE * 4u, Atile, Btile, K, (kc + 1) * G_BK, tid);
            cp_commit();
            cp_wait<1>();
        } else {
            cp_wait<0>();
        }
        __syncthreads();   // stage cur visible to all

        const float* As = sm + cur * G_STAGE;
        const float* Bs = As + G_PLANE;

#pragma unroll
        for (int ks = 0; ks < 4; ks++) {
            int kk = ks * 8;
            float Ah[4][4];
#pragma unroll
            for (int mi = 0; mi < 4; mi++) {
                int mrow = wm * 64 + mi * 16 + gid;
                int base = mrow * G_SK + kk + tig;
                Ah[mi][0] = As[base];
                Ah[mi][1] = As[base + 8 * G_SK];
                Ah[mi][2] = As[base + 4];
                Ah[mi][3] = As[base + 8 * G_SK + 4];
            }
            float Bh[4][2];
#pragma unroll
            for (int ni = 0; ni < 4; ni++) {
                int ncol = wn * 32 + ni * 8 + gid;
                int base = ncol * G_SK + kk + tig;
                Bh[ni][0] = Bs[base];
                Bh[ni][1] = Bs[base + 4];
            }
#pragma unroll
            for (int mi = 0; mi < 4; mi++)
#pragma unroll
                for (int ni = 0; ni < 4; ni++)
                    mma_tf32(acc[mi][ni], Ah[mi][0], Ah[mi][1], Ah[mi][2], Ah[mi][3],
                             Bh[ni][0], Bh[ni][1]);
        }
        __syncthreads();   // all reads of stage cur done before refill
    }

    // epilogue
#pragma unroll
    for (int mi = 0; mi < 4; mi++) {
        int row0 = blockIdx.y * G_BM + wm * 64 + mi * 16 + gid;
#pragma unroll
        for (int ni = 0; ni < 4; ni++) {
            int col = blockIdx.x * G_BN + wn * 32 + ni * 8 + 2 * tig;
            float* d0 = Cm + (size_t)row0 * N + col;
            float* d1 = Cm + (size_t)(row0 + 8) * N + col;
            float2 v0 = make_float2(acc[mi][ni][0], acc[mi][ni][1]);
            float2 v1 = make_float2(acc[mi][ni][2], acc[mi][ni][3]);
            if (Res) {
                const float2 r0 = *reinterpret_cast<const float2*>(Res + (size_t)row0 * N + col);
                const float2 r1 = *reinterpret_cast<const float2*>(Res + (size_t)(row0 + 8) * N + col);
                v0.x += r0.x; v0.y += r0.y;
                v1.x += r1.x; v1.y += r1.y;
            }
            *reinterpret_cast<float2*>(d0) = v0;
            *reinterpret_cast<float2*>(d1) = v1;
        }
    }
}

// ---------------- RMSNorm (output rounded to tf32 — GEMM A operand) ----------
__global__ void rmsnorm_kernel(const float* __restrict__ x,
                               const float* __restrict__ w,
                               float* __restrict__ out)
{
    int row = blockIdx.x;
    const float4* xr = reinterpret_cast<const float4*>(x + (size_t)row * C_DIM);
    float ss = 0.f;
    for (int i = threadIdx.x; i < C_DIM / 4; i += blockDim.x) {
        float4 v = xr[i];
        ss += v.x * v.x + v.y * v.y + v.z * v.z + v.w * v.w;
    }
#pragma unroll
    for (int o = 16; o; o >>= 1) ss += __shfl_xor_sync(0xffffffffu, ss, o);

    __shared__ float red[8];
    __shared__ float s_inv;
    if ((threadIdx.x & 31) == 0) red[threadIdx.x >> 5] = ss;
    __syncthreads();
    if (threadIdx.x == 0) {
        float tot = 0.f;
        int nw = blockDim.x >> 5;
        for (int i = 0; i < nw; i++) tot += red[i];
        s_inv = rsqrtf(tot * (1.0f / C_DIM) + 1e-6f);
    }
    __syncthreads();
    float inv = s_inv;
    const float4* wr = reinterpret_cast<const float4*>(w);
    float4* outr = reinterpret_cast<float4*>(out + (size_t)row * C_DIM);
    for (int i = threadIdx.x; i < C_DIM / 4; i += blockDim.x) {
        float4 v = xr[i], ww = wr[i];
        v.x = to_tf32(v.x * inv * ww.x);
        v.y = to_tf32(v.y * inv * ww.y);
        v.z = to_tf32(v.z * inv * ww.z);
        v.w = to_tf32(v.w * inv * ww.w);
        outr[i] = v;
    }
}

// ---------------- RoPE (applied to q and k in place) -------------------------
__global__ void rope_kernel(float* __restrict__ q, float* __restrict__ k)
{
    int idx = blockIdx.x * blockDim.x + threadIdx.x;
    if (idx >= T_SEQ * NHEADS * 32) return;
    int i = idx & 31;
    int h = (idx >> 5) & (NHEADS - 1);
    int t = idx >> 9;
    float freq = powf(10000.0f, -(float)(2 * i) * (1.0f / 64.0f));
    float f = (float)t * freq;
    float s, c;
    sincosf(f, &s, &c);
    int base = t * C_DIM + h * HDIM;
    float q1 = q[base + i], q2 = q[base + i + 32];
    q[base + i]      = q1 * c - q2 * s;
    q[base + i + 32] = q2 * c + q1 * s;
    float k1 = k[base + i], k2 = k[base + i + 32];
    k[base + i]      = k1 * c - k2 * s;
    k[base + i + 32] = k2 * c + k1 * s;
}

// ---------------- Flash attention on tensor cores ----------------------------
// (R10 configuration: Br=Bc=64, 4 warps, 1-term QK^T, occ=3.)
// Epilogue rounds att to tf32 (it is the A operand of the O projection).
#define FQ_STR 68
#define FV_STR 72
#define F_SMEM_BYTES ((3 * 64 * FQ_STR + 64 * FV_STR) * 4)   // 70656

__global__ __launch_bounds__(128, 3)
void flash_mma_kernel(const float* __restrict__ Qg, const float* __restrict__ Kg,
                      const float* __restrict__ Vg, float* __restrict__ Og)
{
    extern __shared__ float sm[];
    float* Qs = sm;
    float* Kh = Qs + 64 * FQ_STR;
    float* Ps = Kh + 64 * FQ_STR;
    float* Vs = Ps + 64 * FQ_STR;

    int qt = (gridDim.x - 1) - blockIdx.x;   // heavy tiles first
    int h  = blockIdx.y;
    int tid = threadIdx.x;
    int wid = tid >> 5;
    int lane = tid & 31;
    int gid = lane >> 2;
    int tig = lane & 3;
    int wr0 = wid * 16;

#pragma unroll
    for (int v = 0; v < 8; v++) {
        int i = tid + v * 128;
        int row = i >> 4;
        int c4 = i & 15;
        float4 q4 = *reinterpret_cast<const float4*>(
            Qg + (size_t)(qt * 64 + row) * C_DIM + h * HDIM + c4 * 4);
        q4.x = to_tf32(q4.x * 0.125f);
        q4.y = to_tf32(q4.y * 0.125f);
        q4.z = to_tf32(q4.z * 0.125f);
        q4.w = to_tf32(q4.w * 0.125f);
        *reinterpret_cast<float4*>(Qs + row * FQ_STR + c4 * 4) = q4;
    }

    float oacc[8][4];
#pragma unroll
    for (int ni = 0; ni < 8; ni++)
#pragma unroll
        for (int e = 0; e < 4; e++) oacc[ni][e] = 0.f;
    float m0 = -INFINITY, m1 = -INFINITY;
    float l0 = 0.f, l1 = 0.f;

    for (int j = 0; j <= qt; j++) {
        __syncthreads();

#pragma unroll
        for (int v = 0; v < 8; v++) {
            int i = tid + v * 128;
            int row = i >> 4;
            int c4 = i & 15;
            float4 k4 = *reinterpret_cast<const float4*>(
                Kg + (size_t)(j * 64 + row) * C_DIM + h * HDIM + c4 * 4);
            k4.x = to_tf32(k4.x); k4.y = to_tf32(k4.y);
            k4.z = to_tf32(k4.z); k4.w = to_tf32(k4.w);
            *reinterpret_cast<float4*>(Kh + row * FQ_STR + c4 * 4) = k4;
            float4 v4 = *reinterpret_cast<const float4*>(
                Vg + (size_t)(j * 64 + row) * C_DIM + h * HDIM + c4 * 4);
            v4.x = to_tf32(v4.x); v4.y = to_tf32(v4.y);
            v4.z = to_tf32(v4.z); v4.w = to_tf32(v4.w);
            *reinterpret_cast<float4*>(Vs + row * FV_STR + c4 * 4) = v4;
        }
        __syncthreads();

        float sacc[8][4];
#pragma unroll
        for (int ni = 0; ni < 8; ni++)
#pragma unroll
            for (int e = 0; e < 4; e++) sacc[ni][e] = 0.f;

#pragma unroll
        for (int kk = 0; kk < 8; kk++) {
            int kb = kk * 8;
            int abase = (wr0 + gid) * FQ_STR + kb + tig;
            float q0 = Qs[abase];
            float q1 = Qs[abase + 8 * FQ_STR];
            float q2 = Qs[abase + 4];
            float q3 = Qs[abase + 8 * FQ_STR + 4];
#pragma unroll
            for (int ni = 0; ni < 8; ni++) {
                int bbase = (ni * 8 + gid) * FQ_STR + kb + tig;
                float b0 = Kh[bbase];
                float b1 = Kh[bbase + 4];
                mma_tf32(sacc[ni], q0, q1, q2, q3, b0, b1);
            }
        }

        if (j == qt) {
#pragma unroll
            for (int ni = 0; ni < 8; ni++) {
                int c0 = ni * 8 + 2 * tig;
                int rA = wr0 + gid, rB = wr0 + gid + 8;
                if (c0 > rA)     sacc[ni][0] = -INFINITY;
                if (c0 + 1 > rA) sacc[ni][1] = -INFINITY;
                if (c0 > rB)     sacc[ni][2] = -INFINITY;
                if (c0 + 1 > rB) sacc[ni][3] = -INFINITY;
            }
        }

        float rm0 = -INFINITY, rm1 = -INFINITY;
#pragma unroll
        for (int ni = 0; ni < 8; ni++) {
            rm0 = fmaxf(rm0, fmaxf(sacc[ni][0], sacc[ni][1]));
            rm1 = fmaxf(rm1, fmaxf(sacc[ni][2], sacc[ni][3]));
        }
        rm0 = fmaxf(rm0, __shfl_xor_sync(0xffffffffu, rm0, 1));
        rm0 = fmaxf(rm0, __shfl_xor_sync(0xffffffffu, rm0, 2));
        rm1 = fmaxf(rm1, __shfl_xor_sync(0xffffffffu, rm1, 1));
        rm1 = fmaxf(rm1, __shfl_xor_sync(0xffffffffu, rm1, 2));

        float mn0 = fmaxf(m0, rm0);
        float mn1 = fmaxf(m1, rm1);
        float alpha0 = __expf(m0 - mn0);
        float alpha1 = __expf(m1 - mn1);
        m0 = mn0; m1 = mn1;

        float rs0 = 0.f, rs1 = 0.f;
#pragma unroll
        for (int ni = 0; ni < 8; ni++) {
            float p0 = __expf(sacc[ni][0] - mn0);
            float p1 = __expf(sacc[ni][1] - mn0);
            float p2 = __expf(sacc[ni][2] - mn1);
            float p3 = __expf(sacc[ni][3] - mn1);
            rs0 += p0 + p1;
            rs1 += p2 + p3;
            int c0 = ni * 8 + 2 * tig;
            *reinterpret_cast<float2*>(Ps + (wr0 + gid) * FQ_STR + c0) =
                make_float2(to_tf32(p0), to_tf32(p1));
            *reinterpret_cast<float2*>(Ps + (wr0 + gid + 8) * FQ_STR + c0) =
                make_float2(to_tf32(p2), to_tf32(p3));
        }
        rs0 += __shfl_xor_sync(0xffffffffu, rs0, 1);
        rs0 += __shfl_xor_sync(0xffffffffu, rs0, 2);
        rs1 += __shfl_xor_sync(0xffffffffu, rs1, 1);
        rs1 += __shfl_xor_sync(0xffffffffu, rs1, 2);
        l0 = l0 * alpha0 + rs0;
        l1 = l1 * alpha1 + rs1;

#pragma unroll
        for (int ni = 0; ni < 8; ni++) {
            oacc[ni][0] *= alpha0; oacc[ni][1] *= alpha0;
            oacc[ni][2] *= alpha1; oacc[ni][3] *= alpha1;
        }
        __syncwarp();

#pragma unroll
        for (int kk = 0; kk < 8; kk++) {
            int kb = kk * 8;
            int abase = (wr0 + gid) * FQ_STR + kb + tig;
            float a0 = Ps[abase];
            float a1 = Ps[abase + 8 * FQ_STR];
            float a2 = Ps[abase + 4];
            float a3 = Ps[abase + 8 * FQ_STR + 4];
#pragma unroll
            for (int ni = 0; ni < 8; ni++) {
                float b0 = Vs[(kb + tig) * FV_STR + ni * 8 + gid];
                float b1 = Vs[(kb + tig + 4) * FV_STR + ni * 8 + gid];
                mma_tf32(oacc[ni], a0, a1, a2, a3, b0, b1);
            }
        }
    }

    float invl0 = 1.f / l0;
    float invl1 = 1.f / l1;
    int row0 = qt * 64 + wr0 + gid;
    int row1 = row0 + 8;
#pragma unroll
    for (int ni = 0; ni < 8; ni++) {
        int col = h * HDIM + ni * 8 + 2 * tig;
        *reinterpret_cast<float2*>(Og + (size_t)row0 * C_DIM + col) =
            make_float2(to_tf32(oacc[ni][0] * invl0), to_tf32(oacc[ni][1] * invl0));
        *reinterpret_cast<float2*>(Og + (size_t)row1 * C_DIM + col) =
            make_float2(to_tf32(oacc[ni][2] * invl1), to_tf32(oacc[ni][3] * invl1));
    }
}

// ---------------- launch -----------------------------------------------------
extern "C" void kernel_launch(void* const* d_in, const int* in_sizes, int n_in,
                              void* d_out, int out_size)
{
    const float* x      = (const float*)d_in[0];
    const float* wq     = (const float*)d_in[1];
    const float* wk     = (const float*)d_in[2];
    const float* wv     = (const float*)d_in[3];
    const float* wo     = (const float*)d_in[4];
    const float* norm_w = (const float*)d_in[5];
    float* out = (float*)d_out;

    float *normed, *q, *k, *v, *att, *wr;
    cudaGetSymbolAddress((void**)&normed, g_normed);
    cudaGetSymbolAddress((void**)&q,      g_q);
    cudaGetSymbolAddress((void**)&k,      g_k);
    cudaGetSymbolAddress((void**)&v,      g_v);
    cudaGetSymbolAddress((void**)&att,    g_att);
    cudaGetSymbolAddress((void**)&wr,     g_wr);
    float* wqr = wr + 0 * C_DIM * C_DIM;
    float* wkr = wr + 1 * C_DIM * C_DIM;
    float* wvr = wr + 2 * C_DIM * C_DIM;
    float* wor = wr + 3 * C_DIM * C_DIM;

    // 0) round weights to tf32 once (B operands of all GEMMs)
    int n4 = C_DIM * C_DIM / 4;
    int rgrid = (n4 + 255) / 256;
    round_tf32_kernel<<<rgrid, 256>>>(wq, wqr, n4);
    round_tf32_kernel<<<rgrid, 256>>>(wk, wkr, n4);
    round_tf32_kernel<<<rgrid, 256>>>(wv, wvr, n4);
    round_tf32_kernel<<<rgrid, 256>>>(wo, wor, n4);

    // 1) RMSNorm (emits tf32-rounded A operand)
    rmsnorm_kernel<<<T_SEQ, 256>>>(x, norm_w, normed);

    // 2) Q/K/V projections: pure tf32, cp.async pipeline, occ=2 (single wave)
    cudaFuncSetAttribute(gemm_mma_kernel, cudaFuncAttributeMaxDynamicSharedMemorySize,
                         G_SMEM_TOTAL);
    dim3 gdim(C_DIM / G_BN, T_SEQ / G_BM);
    gemm_mma_kernel<<<gdim, 256, G_SMEM_TOTAL>>>(normed, wqr, nullptr, q, T_SEQ, C_DIM, C_DIM);
    gemm_mma_kernel<<<gdim, 256, G_SMEM_TOTAL>>>(normed, wkr, nullptr, k, T_SEQ, C_DIM, C_DIM);
    gemm_mma_kernel<<<gdim, 256, G_SMEM_TOTAL>>>(normed, wvr, nullptr, v, T_SEQ, C_DIM, C_DIM);

    // 3) RoPE on q,k
    int nrope = T_SEQ * NHEADS * 32;
    rope_kernel<<<(nrope + 255) / 256, 256>>>(q, k);

    // 4) causal flash attention (R10 config, rounds att in epilogue)
    cudaFuncSetAttribute(flash_mma_kernel, cudaFuncAttributeMaxDynamicSharedMemorySize,
                         F_SMEM_BYTES);
    dim3 fgrid(T_SEQ / 64, NHEADS);
    flash_mma_kernel<<<fgrid, 128, F_SMEM_BYTES>>>(q, k, v, att);

    // 5) output projection + residual
    gemm_mma_kernel<<<gdim, 256, G_SMEM_TOTAL>>>(att, wor, x, out, T_SEQ, C_DIM, C_DIM);
}

// round 13
// speedup vs baseline: 1.5735x; 1.0532x over previous
#include <cuda_runtime.h>
#include <math.h>
#include <stdint.h>

#define T_SEQ   4096
#define C_DIM   1024
#define NHEADS  16
#define HDIM    64

// ---------------- scratch (static device globals; no allocation) -------------
__device__ float g_normed[T_SEQ * C_DIM];
__device__ float g_q[T_SEQ * C_DIM];
__device__ float g_k[T_SEQ * C_DIM];
__device__ float g_v[T_SEQ * C_DIM];
__device__ float g_att[T_SEQ * C_DIM];
__device__ float g_wr[4][C_DIM * C_DIM];   // tf32-rounded weights

// ================= helpers ===================================================
__device__ __forceinline__ uint32_t smem_u32(const void* p) {
    uint32_t a;
    asm("{ .reg .u64 t; cvta.to.shared.u64 t, %1; cvt.u32.u64 %0, t; }"
        : "=r"(a) : "l"(p));
    return a;
}

__device__ __forceinline__ void cp_async16(uint32_t saddr, const void* gptr) {
    asm volatile("cp.async.cg.shared.global [%0], [%1], 16;"
                 :: "r"(saddr), "l"(gptr));
}
__device__ __forceinline__ void cp_commit() {
    asm volatile("cp.async.commit_group;");
}
template <int N>
__device__ __forceinline__ void cp_wait() {
    asm volatile("cp.async.wait_group %0;" :: "n"(N));
}

__device__ __forceinline__ float to_tf32(float a)
{
    uint32_t u;
    asm("cvt.rna.tf32.f32 %0, %1;" : "=r"(u) : "f"(a));
    return __uint_as_float(u);
}

// m16n8k8 tf32 mma
__device__ __forceinline__ void mma_tf32(float d[4],
                                         float a0, float a1, float a2, float a3,
                                         float b0, float b1)
{
    asm volatile(
        "mma.sync.aligned.m16n8k8.row.col.f32.tf32.tf32.f32 "
        "{%0,%1,%2,%3}, {%4,%5,%6,%7}, {%8,%9}, {%0,%1,%2,%3};"
        : "+f"(d[0]), "+f"(d[1]), "+f"(d[2]), "+f"(d[3])
        : "r"(__float_as_uint(a0)), "r"(__float_as_uint(a1)),
          "r"(__float_as_uint(a2)), "r"(__float_as_uint(a3)),
          "r"(__float_as_uint(b0)), "r"(__float_as_uint(b1)));
}

// ---------------- batched tf32 rounding of the 4 weight matrices -------------
__global__ void round_weights_kernel(const float* __restrict__ w0,
                                     const float* __restrict__ w1,
                                     const float* __restrict__ w2,
                                     const float* __restrict__ w3,
                                     float* __restrict__ outbase, int n4)
{
    int i = blockIdx.x * blockDim.x + threadIdx.x;
    if (i >= n4) return;
    int wsel = blockIdx.y;
    const float* in = (wsel == 0) ? w0 : (wsel == 1) ? w1 : (wsel == 2) ? w2 : w3;
    float* out = outbase + (size_t)wsel * C_DIM * C_DIM;
    float4 v = reinterpret_cast<const float4*>(in)[i];
    v.x = to_tf32(v.x); v.y = to_tf32(v.y);
    v.z = to_tf32(v.z); v.w = to_tf32(v.w);
    reinterpret_cast<float4*>(out)[i] = v;
}

// ================= HMMA tf32 GEMM body (pre-rounded inputs) ==================
// 128x128 CTA tile, BK=32, 8 warps (2x4), warp tile 64x32, cp.async staging,
// occ=2.
#define G_BM 128
#define G_BN 128
#define G_BK 32
#define G_SK 36
#define G_PLANE (128 * G_SK)
#define G_STAGE (2 * G_PLANE)
#define G_SMEM_TOTAL (2 * G_STAGE * 4)        // 73728 bytes

__device__ __forceinline__ void issue_tile(uint32_t s_a, uint32_t s_b,
                                           const float* __restrict__ Ag,
                                           const float* __restrict__ Bg,
                                           int K, int k0, int tid)
{
#pragma unroll
    for (int t = 0; t < 4; t++) {
        int idx = tid + t * 256;
        int row = idx >> 3;
        int c4 = idx & 7;
        uint32_t soff = (uint32_t)(row * G_SK + c4 * 4) * 4u;
        cp_async16(s_a + soff, Ag + (size_t)row * K + k0 + c4 * 4);
        cp_async16(s_b + soff, Bg + (size_t)row * K + k0 + c4 * 4);
    }
}

__device__ __forceinline__ void gemm_body(const float* __restrict__ A,
                                          const float* __restrict__ B,
                                          const float* __restrict__ Res,
                                          float* __restrict__ Cm,
                                          int M, int N, int K,
                                          int bx, int by, float* sm)
{
    uint32_t smem_base = smem_u32(sm);
    int tid = threadIdx.x;
    int wid = tid >> 5;
    int lane = tid & 31;
    int gid = lane >> 2;
    int tig = lane & 3;
    int wm = wid & 1;
    int wn = wid >> 1;

    const float* Atile = A + (size_t)(by * G_BM) * K;
    const float* Btile = B + (size_t)(bx * G_BN) * K;

    float acc[4][4][4];
#pragma unroll
    for (int mi = 0; mi < 4; mi++)
#pragma unroll
        for (int ni = 0; ni < 4; ni++)
#pragma unroll
            for (int e = 0; e < 4; e++) acc[mi][ni][e] = 0.f;

    const int NCHUNK = K / G_BK;

    issue_tile(smem_base, smem_base + G_PLANE * 4u, Atile, Btile, K, 0, tid);
    cp_commit();

    for (int kc = 0; kc < NCHUNK; kc++) {
        int cur = kc & 1;
        if (kc + 1 < NCHUNK) {
            uint32_t sb = smem_base + (uint32_t)(1 - cur) * G_STAGE * 4u;
            issue_tile(sb, sb + G_PLANE * 4u, Atile, Btile, K, (kc + 1) * G_BK, tid);
            cp_commit();
            cp_wait<1>();
        } else {
            cp_wait<0>();
        }
        __syncthreads();

        const float* As = sm + cur * G_STAGE;
        const float* Bs = As + G_PLANE;

#pragma unroll
        for (int ks = 0; ks < 4; ks++) {
            int kk = ks * 8;
            float Ah[4][4];
#pragma unroll
            for (int mi = 0; mi < 4; mi++) {
                int mrow = wm * 64 + mi * 16 + gid;
                int base = mrow * G_SK + kk + tig;
                Ah[mi][0] = As[base];
                Ah[mi][1] = As[base + 8 * G_SK];
                Ah[mi][2] = As[base + 4];
                Ah[mi][3] = As[base + 8 * G_SK + 4];
            }
            float Bh[4][2];
#pragma unroll
            for (int ni = 0; ni < 4; ni++) {
                int ncol = wn * 32 + ni * 8 + gid;
                int base = ncol * G_SK + kk + tig;
                Bh[ni][0] = Bs[base];
                Bh[ni][1] = Bs[base + 4];
            }
#pragma unroll
            for (int mi = 0; mi < 4; mi++)
#pragma unroll
                for (int ni = 0; ni < 4; ni++)
                    mma_tf32(acc[mi][ni], Ah[mi][0], Ah[mi][1], Ah[mi][2], Ah[mi][3],
                             Bh[ni][0], Bh[ni][1]);
        }
        __syncthreads();
    }

#pragma unroll
    for (int mi = 0; mi < 4; mi++) {
        int row0 = by * G_BM + wm * 64 + mi * 16 + gid;
#pragma unroll
        for (int ni = 0; ni < 4; ni++) {
            int col = bx * G_BN + wn * 32 + ni * 8 + 2 * tig;
            float* d0 = Cm + (size_t)row0 * N + col;
            float* d1 = Cm + (size_t)(row0 + 8) * N + col;
            float2 v0 = make_float2(acc[mi][ni][0], acc[mi][ni][1]);
            float2 v1 = make_float2(acc[mi][ni][2], acc[mi][ni][3]);
            if (Res) {
                const float2 r0 = *reinterpret_cast<const float2*>(Res + (size_t)row0 * N + col);
                const float2 r1 = *reinterpret_cast<const float2*>(Res + (size_t)(row0 + 8) * N + col);
                v0.x += r0.x; v0.y += r0.y;
                v1.x += r1.x; v1.y += r1.y;
            }
            *reinterpret_cast<float2*>(d0) = v0;
            *reinterpret_cast<float2*>(d1) = v1;
        }
    }
}

// batched QKV: blockIdx.z selects (wq->q, wk->k, wv->v); shared A
__global__ __launch_bounds__(256, 2)
void gemm_qkv_kernel(const float* __restrict__ A,
                     const float* __restrict__ b0, const float* __restrict__ b1,
                     const float* __restrict__ b2,
                     float* __restrict__ c0, float* __restrict__ c1,
                     float* __restrict__ c2)
{
    extern __shared__ float sm[];
    int z = blockIdx.z;
    const float* B = (z == 0) ? b0 : (z == 1) ? b1 : b2;
    float* Cm = (z == 0) ? c0 : (z == 1) ? c1 : c2;
    gemm_body(A, B, nullptr, Cm, T_SEQ, C_DIM, C_DIM, blockIdx.x, blockIdx.y, sm);
}

__global__ __launch_bounds__(256, 2)
void gemm_mma_kernel(const float* __restrict__ A, const float* __restrict__ B,
                     const float* __restrict__ Res, float* __restrict__ Cm,
                     int M, int N, int K)
{
    extern __shared__ float sm[];
    gemm_body(A, B, Res, Cm, M, N, K, blockIdx.x, blockIdx.y, sm);
}

// ---------------- RMSNorm (output rounded to tf32 — GEMM A operand) ----------
__global__ void rmsnorm_kernel(const float* __restrict__ x,
                               const float* __restrict__ w,
                               float* __restrict__ out)
{
    int row = blockIdx.x;
    const float4* xr = reinterpret_cast<const float4*>(x + (size_t)row * C_DIM);
    float ss = 0.f;
    for (int i = threadIdx.x; i < C_DIM / 4; i += blockDim.x) {
        float4 v = xr[i];
        ss += v.x * v.x + v.y * v.y + v.z * v.z + v.w * v.w;
    }
#pragma unroll
    for (int o = 16; o; o >>= 1) ss += __shfl_xor_sync(0xffffffffu, ss, o);

    __shared__ float red[8];
    __shared__ float s_inv;
    if ((threadIdx.x & 31) == 0) red[threadIdx.x >> 5] = ss;
    __syncthreads();
    if (threadIdx.x == 0) {
        float tot = 0.f;
        int nw = blockDim.x >> 5;
        for (int i = 0; i < nw; i++) tot += red[i];
        s_inv = rsqrtf(tot * (1.0f / C_DIM) + 1e-6f);
    }
    __syncthreads();
    float inv = s_inv;
    const float4* wr = reinterpret_cast<const float4*>(w);
    float4* outr = reinterpret_cast<float4*>(out + (size_t)row * C_DIM);
    for (int i = threadIdx.x; i < C_DIM / 4; i += blockDim.x) {
        float4 v = xr[i], ww = wr[i];
        v.x = to_tf32(v.x * inv * ww.x);
        v.y = to_tf32(v.y * inv * ww.y);
        v.z = to_tf32(v.z * inv * ww.z);
        v.w = to_tf32(v.w * inv * ww.w);
        outr[i] = v;
    }
}

// ---------------- RoPE + flash-operand rounding ------------------------------
// q <- tf32(rot(q) * 0.125); k <- tf32(rot(k)); v <- tf32(v).
__global__ void rope_kernel(float* __restrict__ q, float* __restrict__ k,
                            float* __restrict__ v)
{
    int idx = blockIdx.x * blockDim.x + threadIdx.x;
    if (idx >= T_SEQ * NHEADS * 32) return;
    int i = idx & 31;
    int h = (idx >> 5) & (NHEADS - 1);
    int t = idx >> 9;
    float freq = powf(10000.0f, -(float)(2 * i) * (1.0f / 64.0f));
    float f = (float)t * freq;
    float s, c;
    sincosf(f, &s, &c);
    int base = t * C_DIM + h * HDIM;
    float q1 = q[base + i], q2 = q[base + i + 32];
    q[base + i]      = to_tf32((q1 * c - q2 * s) * 0.125f);
    q[base + i + 32] = to_tf32((q2 * c + q1 * s) * 0.125f);
    float k1 = k[base + i], k2 = k[base + i + 32];
    k[base + i]      = to_tf32(k1 * c - k2 * s);
    k[base + i + 32] = to_tf32(k2 * c + k1 * s);
    v[base + i]      = to_tf32(v[base + i]);
    v[base + i + 32] = to_tf32(v[base + i + 32]);
}

// ---------------- Flash attention on tensor cores ----------------------------
// Br=Bc=64, 4 warps, 1-term tf32, occ=3. Inputs pre-rounded; K/V via cp.async.
#define FQ_STR 68
#define FV_STR 72
#define F_SMEM_BYTES ((3 * 64 * FQ_STR + 64 * FV_STR) * 4)   // 70656

__global__ __launch_bounds__(128, 3)
void flash_mma_kernel(const float* __restrict__ Qg, const float* __restrict__ Kg,
                      const float* __restrict__ Vg, float* __restrict__ Og)
{
    extern __shared__ float sm[];
    float* Qs = sm;
    float* Kh = Qs + 64 * FQ_STR;
    float* Ps = Kh + 64 * FQ_STR;
    float* Vs = Ps + 64 * FQ_STR;
    uint32_t kh_base = smem_u32(Kh);
    uint32_t vs_base = smem_u32(Vs);

    int qt = (gridDim.x - 1) - blockIdx.x;   // heavy tiles first
    int h  = blockIdx.y;
    int tid = threadIdx.x;
    int wid = tid >> 5;
    int lane = tid & 31;
    int gid = lane >> 2;
    int tig = lane & 3;
    int wr0 = wid * 16;

    // ---- load Q tile (already scaled+rounded by rope) ----
#pragma unroll
    for (int v = 0; v < 8; v++) {
        int i = tid + v * 128;
        int row = i >> 4;
        int c4 = i & 15;
        *reinterpret_cast<float4*>(Qs + row * FQ_STR + c4 * 4) =
            *reinterpret_cast<const float4*>(
                Qg + (size_t)(qt * 64 + row) * C_DIM + h * HDIM + c4 * 4);
    }

    float oacc[8][4];
#pragma unroll
    for (int ni = 0; ni < 8; ni++)
#pragma unroll
        for (int e = 0; e < 4; e++) oacc[ni][e] = 0.f;
    float m0 = -INFINITY, m1 = -INFINITY;
    float l0 = 0.f, l1 = 0.f;

    for (int j = 0; j <= qt; j++) {
        __syncthreads();   // previous tile's smem reads complete (and Q on iter 0)

        // ---- stage K and V tiles via cp.async (pre-rounded data) ----
#pragma unroll
        for (int t = 0; t < 8; t++) {
            int i = tid + t * 128;        // 1024 float4 per 64x64 tile
            int row = i >> 4;
            int c4 = i & 15;
            const float* kg = Kg + (size_t)(j * 64 + row) * C_DIM + h * HDIM + c4 * 4;
            const float* vg = Vg + (size_t)(j * 64 + row) * C_DIM + h * HDIM + c4 * 4;
            cp_async16(kh_base + (uint32_t)(row * FQ_STR + c4 * 4) * 4u, kg);
            cp_async16(vs_base + (uint32_t)(row * FV_STR + c4 * 4) * 4u, vg);
        }
        cp_commit();
        cp_wait<0>();
        __syncthreads();

        // ---- S = Q K^T ----
        float sacc[8][4];
#pragma unroll
        for (int ni = 0; ni < 8; ni++)
#pragma unroll
            for (int e = 0; e < 4; e++) sacc[ni][e] = 0.f;

#pragma unroll
        for (int kk = 0; kk < 8; kk++) {
            int kb = kk * 8;
            int abase = (wr0 + gid) * FQ_STR + kb + tig;
            float q0 = Qs[abase];
            float q1 = Qs[abase + 8 * FQ_STR];
            float q2 = Qs[abase + 4];
            float q3 = Qs[abase + 8 * FQ_STR + 4];
#pragma unroll
            for (int ni = 0; ni < 8; ni++) {
                int bbase = (ni * 8 + gid) * FQ_STR + kb + tig;
                float b0 = Kh[bbase];
                float b1 = Kh[bbase + 4];
                mma_tf32(sacc[ni], q0, q1, q2, q3, b0, b1);
            }
        }

        if (j == qt) {
#pragma unroll
            for (int ni = 0; ni < 8; ni++) {
                int c0 = ni * 8 + 2 * tig;
                int rA = wr0 + gid, rB = wr0 + gid + 8;
                if (c0 > rA)     sacc[ni][0] = -INFINITY;
                if (c0 + 1 > rA) sacc[ni][1] = -INFINITY;
                if (c0 > rB)     sacc[ni][2] = -INFINITY;
                if (c0 + 1 > rB) sacc[ni][3] = -INFINITY;
            }
        }

        float rm0 = -INFINITY, rm1 = -INFINITY;
#pragma unroll
        for (int ni = 0; ni < 8; ni++) {
            rm0 = fmaxf(rm0, fmaxf(sacc[ni][0], sacc[ni][1]));
            rm1 = fmaxf(rm1, fmaxf(sacc[ni][2], sacc[ni][3]));
        }
        rm0 = fmaxf(rm0, __shfl_xor_sync(0xffffffffu, rm0, 1));
        rm0 = fmaxf(rm0, __shfl_xor_sync(0xffffffffu, rm0, 2));
        rm1 = fmaxf(rm1, __shfl_xor_sync(0xffffffffu, rm1, 1));
        rm1 = fmaxf(rm1, __shfl_xor_sync(0xffffffffu, rm1, 2));

        float mn0 = fmaxf(m0, rm0);
        float mn1 = fmaxf(m1, rm1);
        float alpha0 = __expf(m0 - mn0);
        float alpha1 = __expf(m1 - mn1);
        m0 = mn0; m1 = mn1;

        float rs0 = 0.f, rs1 = 0.f;
#pragma unroll
        for (int ni = 0; ni < 8; ni++) {
            float p0 = __expf(sacc[ni][0] - mn0);
            float p1 = __expf(sacc[ni][1] - mn0);
            float p2 = __expf(sacc[ni][2] - mn1);
            float p3 = __expf(sacc[ni][3] - mn1);
            rs0 += p0 + p1;
            rs1 += p2 + p3;
            int c0 = ni * 8 + 2 * tig;
            *reinterpret_cast<float2*>(Ps + (wr0 + gid) * FQ_STR + c0) =
                make_float2(to_tf32(p0), to_tf32(p1));
            *reinterpret_cast<float2*>(Ps + (wr0 + gid + 8) * FQ_STR + c0) =
                make_float2(to_tf32(p2), to_tf32(p3));
        }
        rs0 += __shfl_xor_sync(0xffffffffu, rs0, 1);
        rs0 += __shfl_xor_sync(0xffffffffu, rs0, 2);
        rs1 += __shfl_xor_sync(0xffffffffu, rs1, 1);
        rs1 += __shfl_xor_sync(0xffffffffu, rs1, 2);
        l0 = l0 * alpha0 + rs0;
        l1 = l1 * alpha1 + rs1;

#pragma unroll
        for (int ni = 0; ni < 8; ni++) {
            oacc[ni][0] *= alpha0; oacc[ni][1] *= alpha0;
            oacc[ni][2] *= alpha1; oacc[ni][3] *= alpha1;
        }
        __syncwarp();

        // ---- O += P V ----
#pragma unroll
        for (int kk = 0; kk < 8; kk++) {
            int kb = kk * 8;
            int abase = (wr0 + gid) * FQ_STR + kb + tig;
            float a0 = Ps[abase];
            float a1 = Ps[abase + 8 * FQ_STR];
            float a2 = Ps[abase + 4];
            float a3 = Ps[abase + 8 * FQ_STR + 4];
#pragma unroll
            for (int ni = 0; ni < 8; ni++) {
                float b0 = Vs[(kb + tig) * FV_STR + ni * 8 + gid];
                float b1 = Vs[(kb + tig + 4) * FV_STR + ni * 8 + gid];
                mma_tf32(oacc[ni], a0, a1, a2, a3, b0, b1);
            }
        }
    }

    float invl0 = 1.f / l0;
    float invl1 = 1.f / l1;
    int row0 = qt * 64 + wr0 + gid;
    int row1 = row0 + 8;
#pragma unroll
    for (int ni = 0; ni < 8; ni++) {
        int col = h * HDIM + ni * 8 + 2 * tig;
        *reinterpret_cast<float2*>(Og + (size_t)row0 * C_DIM + col) =
            make_float2(to_tf32(oacc[ni][0] * invl0), to_tf32(oacc[ni][1] * invl0));
        *reinterpret_cast<float2*>(Og + (size_t)row1 * C_DIM + col) =
            make_float2(to_tf32(oacc[ni][2] * invl1), to_tf32(oacc[ni][3] * invl1));
    }
}

// ---------------- launch -----------------------------------------------------
extern "C" void kernel_launch(void* const* d_in, const int* in_sizes, int n_in,
                              void* d_out, int out_size)
{
    const float* x      = (const float*)d_in[0];
    const float* wq     = (const float*)d_in[1];
    const float* wk     = (const float*)d_in[2];
    const float* wv     = (const float*)d_in[3];
    const float* wo     = (const float*)d_in[4];
    const float* norm_w = (const float*)d_in[5];
    float* out = (float*)d_out;

    float *normed, *q, *k, *v, *att, *wr;
    cudaGetSymbolAddress((void**)&normed, g_normed);
    cudaGetSymbolAddress((void**)&q,      g_q);
    cudaGetSymbolAddress((void**)&k,      g_k);
    cudaGetSymbolAddress((void**)&v,      g_v);
    cudaGetSymbolAddress((void**)&att,    g_att);
    cudaGetSymbolAddress((void**)&wr,     g_wr);
    float* wqr = wr + 0 * C_DIM * C_DIM;
    float* wkr = wr + 1 * C_DIM * C_DIM;
    float* wvr = wr + 2 * C_DIM * C_DIM;
    float* wor = wr + 3 * C_DIM * C_DIM;

    // 0) round all 4 weight matrices to tf32 in one batched launch
    int n4 = C_DIM * C_DIM / 4;
    dim3 rg((n4 + 255) / 256, 4);
    round_weights_kernel<<<rg, 256>>>(wq, wk, wv, wo, wr, n4);

    // 1) RMSNorm (emits tf32-rounded A operand)
    rmsnorm_kernel<<<T_SEQ, 256>>>(x, norm_w, normed);

    // 2) Q/K/V projections: one batched launch (z selects weight/output)
    cudaFuncSetAttribute(gemm_qkv_kernel, cudaFuncAttributeMaxDynamicSharedMemorySize,
                         G_SMEM_TOTAL);
    cudaFuncSetAttribute(gemm_mma_kernel, cudaFuncAttributeMaxDynamicSharedMemorySize,
                         G_SMEM_TOTAL);
    dim3 gqkv(C_DIM / G_BN, T_SEQ / G_BM, 3);
    gemm_qkv_kernel<<<gqkv, 256, G_SMEM_TOTAL>>>(normed, wqr, wkr, wvr, q, k, v);

    // 3) RoPE + round q/k/v for flash
    int nrope = T_SEQ * NHEADS * 32;
    rope_kernel<<<(nrope + 255) / 256, 256>>>(q, k, v);

    // 4) causal flash attention (conversion-free, cp.async staging)
    cudaFuncSetAttribute(flash_mma_kernel, cudaFuncAttributeMaxDynamicSharedMemorySize,
                         F_SMEM_BYTES);
    dim3 fgrid(T_SEQ / 64, NHEADS);
    flash_mma_kernel<<<fgrid, 128, F_SMEM_BYTES>>>(q, k, v, att);

    // 5) output projection + residual
    dim3 gdim(C_DIM / G_BN, T_SEQ / G_BM);
    gemm_mma_kernel<<<gdim, 256, G_SMEM_TOTAL>>>(att, wor, x, out, T_SEQ, C_DIM, C_DIM);
}